// round 6
// baseline (speedup 1.0000x reference)
#include <cuda_runtime.h>
#include <cuda_bf16.h>
#include <math.h>
#include <stdint.h>

// ---------------- problem constants ----------------
#define BATCH 4096
#define NF    39
#define NE    16
#define NPAIR 741
#define K1    (2 * NPAIR * NE)    // 23712
#define K1P   23744               // padded to multiple of 64
#define HID   400
#define K2P   416                 // HID padded to multiple of 32
#define EPS   1e-5f
#define QMAX  32639.0f

// ---------------- GEMM tiling (shared by i8 and bf16 kernels) ----------------
#define BM 128
#define BN 80
#define A_ROWB 80                 // smem row stride bytes
#define OFF_A0  10240             // 128*80
#define OFF_B1  20480
#define OFF_B0  26880
#define STAGE   33280
#define SMEM_G  (STAGE * 4)       // 133120
#define KSPLIT0 8
#define NB      512               // stat partial blocks
#define SQOFF   (HID * NB)

// ---------------- scratch (static device globals) ----------------
__device__ char d_qa1[(size_t)BATCH * K1P];
__device__ char d_qa0[(size_t)BATCH * K1P];
__device__ char d_qb1[(size_t)HID * K1P];
__device__ char d_qb0[(size_t)HID * K1P];
__device__ float d_ascale[BATCH];
__device__ float d_bscale[HID];
__device__ int d_ph[(size_t)KSPLIT0 * BATCH * HID];
__device__ int d_pm[(size_t)KSPLIT0 * BATCH * HID];
__device__ __nv_bfloat16 d_a2_hi[(size_t)BATCH * K2P];
__device__ __nv_bfloat16 d_a2_lo[(size_t)BATCH * K2P];
__device__ __nv_bfloat16 d_w2_hi[(size_t)HID * K2P];
__device__ __nv_bfloat16 d_w2_lo[(size_t)HID * K2P];
__device__ float d_h0[BATCH * HID];
__device__ float d_h1[BATCH * HID];
__device__ float d_h2[BATCH * HID];
__device__ float d_pstat[2 * NB * HID];
__device__ float d_scale[3][HID];
__device__ float d_shift[3][HID];

// ---------------- helpers ----------------
__device__ __forceinline__ uint32_t smem_u32(const void* p) {
    uint32_t a;
    asm("{ .reg .u64 t; cvta.to.shared.u64 t, %1; cvt.u32.u64 %0, t; }" : "=r"(a) : "l"(p));
    return a;
}

#define CP_ASYNC16(dst, src) \
    asm volatile("cp.async.cg.shared.global [%0], [%1], 16;" :: "r"(dst), "l"(src))
#define CP_COMMIT() asm volatile("cp.async.commit_group;" ::: "memory")
#define CP_WAIT2()  asm volatile("cp.async.wait_group 2;" ::: "memory")
#define CP_WAIT1()  asm volatile("cp.async.wait_group 1;" ::: "memory")
#define CP_WAIT0()  asm volatile("cp.async.wait_group 0;" ::: "memory")

#define LDSM4(r0, r1, r2, r3, a) \
    asm volatile("ldmatrix.sync.aligned.m8n8.x4.shared.b16 {%0,%1,%2,%3}, [%4];" \
        : "=r"(r0), "=r"(r1), "=r"(r2), "=r"(r3) : "r"(a))
#define LDSM2(r0, r1, a) \
    asm volatile("ldmatrix.sync.aligned.m8n8.x2.shared.b16 {%0,%1}, [%2];" \
        : "=r"(r0), "=r"(r1) : "r"(a))

__device__ __forceinline__ void mma_s8(int* c, const uint32_t* a, const uint32_t* b) {
    asm volatile(
        "mma.sync.aligned.m16n8k32.row.col.s32.s8.s8.s32 "
        "{%0,%1,%2,%3}, {%4,%5,%6,%7}, {%8,%9}, {%0,%1,%2,%3};"
        : "+r"(c[0]), "+r"(c[1]), "+r"(c[2]), "+r"(c[3])
        : "r"(a[0]), "r"(a[1]), "r"(a[2]), "r"(a[3]), "r"(b[0]), "r"(b[1]));
}
__device__ __forceinline__ void mma_bf16(float* c, const uint32_t* a, const uint32_t* b) {
    asm volatile(
        "mma.sync.aligned.m16n8k16.row.col.f32.bf16.bf16.f32 "
        "{%0,%1,%2,%3}, {%4,%5,%6,%7}, {%8,%9}, {%0,%1,%2,%3};"
        : "+f"(c[0]), "+f"(c[1]), "+f"(c[2]), "+f"(c[3])
        : "r"(a[0]), "r"(a[1]), "r"(a[2]), "r"(a[3]), "r"(b[0]), "r"(b[1]));
}

__device__ __forceinline__ void split16(int q, char& hi, char& lo) {
    int h = (q + 128) >> 8;
    hi = (char)h;
    lo = (char)(q - (h << 8));
}

// =====================================================================
// Kernel 1: gather + SENET + bilinear -> int8 pair (per-row scaled)
// =====================================================================
__global__ __launch_bounds__(256) void fuse_front(
    const int* __restrict__ x,
    const float* __restrict__ emb,
    const float* __restrict__ w1, const float* __restrict__ b1,
    const float* __restrict__ w2, const float* __restrict__ b2,
    const float* __restrict__ Wb1, const float* __restrict__ Wb2,
    char* __restrict__ qa1, char* __restrict__ qa0,
    float* __restrict__ ascale)
{
    __shared__ float xe[NF][NE];
    __shared__ float xs[NF][NE];
    __shared__ float p1[NF][NE];
    __shared__ float p2[NF][NE];
    __shared__ float zf[NF], av[NF], af[NF];
    __shared__ unsigned char ii[NPAIR], jj[NPAIR];
    __shared__ float red[256];
    __shared__ float s_inv;
    __shared__ int is64;

    const int b = blockIdx.x;
    const int tid = threadIdx.x;

    if (tid == 0) {
        int f64 = 1;
        for (int w = 1; w < 2 * NF; w += 2)
            if (x[w] != 0) { f64 = 0; break; }
        is64 = f64;
    }
    for (int k = tid; k < NPAIR; k += 256) {
        int i = 0, rem = k;
        while (rem >= NF - 1 - i) { rem -= NF - 1 - i; i++; }
        ii[k] = (unsigned char)i;
        jj[k] = (unsigned char)(i + 1 + rem);
    }
    __syncthreads();

    for (int idx = tid; idx < NF * NE; idx += 256) {
        int f = idx >> 4, e = idx & 15;
        int xv = is64 ? x[2 * (b * NF + f)] : x[b * NF + f];
        xe[f][e] = emb[(xv + 1000 * f) * NE + e];
    }
    __syncthreads();

    if (tid < NF) {
        float m = xe[tid][0];
        #pragma unroll
        for (int e = 1; e < NE; e++) m = fmaxf(m, xe[tid][e]);
        zf[tid] = m;
    }
    __syncthreads();
    if (tid < NF) {
        float s = b1[tid];
        for (int j = 0; j < NF; j++) s += zf[j] * w1[tid * NF + j];
        av[tid] = fmaxf(s, 0.0f);
    }
    __syncthreads();
    if (tid < NF) {
        float s = b2[tid];
        for (int j = 0; j < NF; j++) s += av[j] * w2[tid * NF + j];
        af[tid] = fmaxf(s, 0.0f);
    }
    __syncthreads();

    for (int idx = tid; idx < NF * NE; idx += 256) {
        int f = idx >> 4, d = idx & 15;
        float s1 = 0.0f, s2 = 0.0f;
        #pragma unroll
        for (int e = 0; e < NE; e++) {
            float v = xe[f][e];
            s1 += v * Wb1[d * NE + e];
            s2 += v * Wb2[d * NE + e];
        }
        p1[f][d] = s1;
        p2[f][d] = af[f] * s2;
        xs[f][d] = af[f] * xe[f][d];
    }
    __syncthreads();

    // pass 1: row max of |values|
    float mx = 0.0f;
    for (int idx = tid; idx < NPAIR * NE; idx += 256) {
        int k = idx >> 4, e = idx & 15;
        int i = ii[k], j = jj[k];
        mx = fmaxf(mx, fabsf(p1[i][e] * xe[j][e]));
        mx = fmaxf(mx, fabsf(p2[i][e] * xs[j][e]));
    }
    red[tid] = mx;
    __syncthreads();
    for (int o = 128; o > 0; o >>= 1) {
        if (tid < o) red[tid] = fmaxf(red[tid], red[tid + o]);
        __syncthreads();
    }
    if (tid == 0) {
        float rm = red[0];
        ascale[b] = rm / QMAX;
        s_inv = (rm > 0.0f) ? (QMAX / rm) : 0.0f;
    }
    __syncthreads();
    const float inv = s_inv;

    // pass 2: quantize + split + store
    char* o1 = qa1 + (size_t)b * K1P;
    char* o0 = qa0 + (size_t)b * K1P;
    for (int idx = tid; idx < NPAIR * NE; idx += 256) {
        int k = idx >> 4, e = idx & 15;
        int i = ii[k], j = jj[k];
        float v1 = p1[i][e] * xe[j][e];
        float v2 = p2[i][e] * xs[j][e];
        int q1 = __float2int_rn(v1 * inv);
        int q2 = __float2int_rn(v2 * inv);
        q1 = max(-32639, min(32639, q1));
        q2 = max(-32639, min(32639, q2));
        char h, l;
        split16(q1, h, l);
        o1[idx] = h; o0[idx] = l;
        split16(q2, h, l);
        o1[idx + NPAIR * NE] = h; o0[idx + NPAIR * NE] = l;
    }
    // zero pad
    for (int k = K1 + tid; k < K1P; k += 256) { o1[k] = 0; o0[k] = 0; }
}

// =====================================================================
// Kernel 1b: quantize mw0 rows -> int8 pair (per-row scale)
// =====================================================================
__global__ __launch_bounds__(256) void quant_b(
    const float* __restrict__ w, char* __restrict__ qb1,
    char* __restrict__ qb0, float* __restrict__ bscale)
{
    __shared__ float red[256];
    __shared__ float s_inv;
    const int n = blockIdx.x;
    const int tid = threadIdx.x;
    const float* row = w + (size_t)n * K1;

    float mx = 0.0f;
    for (int k = tid; k < K1; k += 256) mx = fmaxf(mx, fabsf(row[k]));
    red[tid] = mx;
    __syncthreads();
    for (int o = 128; o > 0; o >>= 1) {
        if (tid < o) red[tid] = fmaxf(red[tid], red[tid + o]);
        __syncthreads();
    }
    if (tid == 0) {
        float rm = red[0];
        bscale[n] = rm / QMAX;
        s_inv = (rm > 0.0f) ? (QMAX / rm) : 0.0f;
    }
    __syncthreads();
    const float inv = s_inv;

    char* o1 = qb1 + (size_t)n * K1P;
    char* o0 = qb0 + (size_t)n * K1P;
    for (int k = tid; k < K1; k += 256) {
        int q = __float2int_rn(row[k] * inv);
        q = max(-32639, min(32639, q));
        char h, l;
        split16(q, h, l);
        o1[k] = h; o0[k] = l;
    }
    for (int k = K1 + tid; k < K1P; k += 256) { o1[k] = 0; o0[k] = 0; }
}

// =====================================================================
// Kernel 2: GEMM0 int8 (Ozaki split), split-K=8
//   ph[z][m,n] = sum A1*B1 ; pm[z][m,n] = sum (A1*B0 + A0*B1)
//   CTA 128x80, BK=64 int8, 8 warps (4m x 2n), warp 32x40
// =====================================================================
__global__ __launch_bounds__(256, 1) void gemm0_i8(
    const char* __restrict__ a1p, const char* __restrict__ a0p,
    const char* __restrict__ b1p, const char* __restrict__ b0p,
    int* __restrict__ ph, int* __restrict__ pm, int Kst, int ksplit)
{
    extern __shared__ char smem[];
    const uint32_t sb = smem_u32(smem);
    const int tid  = threadIdx.x;
    const int wid  = tid >> 5;
    const int lane = tid & 31;

    const int nbase = blockIdx.x * BN;
    const int mbase = blockIdx.y * BM;
    const int z     = blockIdx.z;

    const int tilesTot = Kst / 64;
    const int qt = tilesTot / ksplit, rt = tilesTot % ksplit;
    const int t0 = z * qt + (z < rt ? z : rt);
    const int T  = qt + (z < rt ? 1 : 0);

    const int wm = (wid & 3) * 32;
    const int wn = (wid >> 2) * 40;
    const int grp = lane >> 2;
    const int qd  = lane & 3;

    const uint32_t aoff = (uint32_t)((wm + (lane & 15)) * A_ROWB + ((lane >> 4) * 16));
    const int rowB = (lane & 7) + ((lane >> 4) << 3);
    const int kB   = ((lane >> 3) & 1) * 16;
    const uint32_t boff  = (uint32_t)(OFF_B1 + (wn + rowB) * A_ROWB + kB);
    const uint32_t boff2 = (uint32_t)(OFF_B1 + (wn + 32 + (lane & 7)) * A_ROWB + kB);

    int accH[2][5][4], accM[2][5][4];
    #pragma unroll
    for (int im = 0; im < 2; im++)
        #pragma unroll
        for (int in = 0; in < 5; in++)
            #pragma unroll
            for (int r = 0; r < 4; r++) { accH[im][in][r] = 0; accM[im][in][r] = 0; }

    auto load_tile = [&](int s, int t) {
        const int k0 = t * 64;
        const uint32_t st = sb + s * STAGE;
        #pragma unroll
        for (int i = 0; i < 2; i++) {                  // A: 512 chunks
            int idx = tid + i * 256;
            int rr = idx >> 2, ch = idx & 3;
            uint32_t dst = st + rr * A_ROWB + ch * 16;
            size_t g = (size_t)(mbase + rr) * Kst + k0 + ch * 16;
            CP_ASYNC16(dst, a1p + g);
            CP_ASYNC16(dst + OFF_A0, a0p + g);
        }
        if (tid < 320) {                               // B: 320 chunks part1
            int rr = tid >> 2, ch = tid & 3;
            uint32_t dst = st + OFF_B1 + rr * A_ROWB + ch * 16;
            size_t g = (size_t)(nbase + rr) * Kst + k0 + ch * 16;
            CP_ASYNC16(dst, b1p + g);
            CP_ASYNC16(dst + 6400, b0p + g);
        }
        if (tid < 64) {                                // B chunks 256..319
            int idx = tid + 256;
            int rr = idx >> 2, ch = idx & 3;
            uint32_t dst = st + OFF_B1 + rr * A_ROWB + ch * 16;
            size_t g = (size_t)(nbase + rr) * Kst + k0 + ch * 16;
            CP_ASYNC16(dst, b1p + g);
            CP_ASYNC16(dst + 6400, b0p + g);
        }
        CP_COMMIT();
    };

    load_tile(0, t0);
    load_tile(1, t0 + 1);
    load_tile(2, t0 + 2);

    for (int u = 0; u < T; ++u) {
        const int rem = T - 1 - u;
        if (rem >= 2) { CP_WAIT2(); } else if (rem == 1) { CP_WAIT1(); } else { CP_WAIT0(); }
        __syncthreads();

        if (u + 3 < T) load_tile((u + 3) & 3, t0 + u + 3);

        const uint32_t sA = sb + (u & 3) * STAGE;
        #pragma unroll
        for (int ks = 0; ks < 2; ks++) {
            const uint32_t ka = ks * 32;
            uint32_t a1[2][4], a0[2][4], b1[5][2], b0[5][2];
            LDSM4(a1[0][0], a1[0][1], a1[0][2], a1[0][3], sA + aoff + ka);
            LDSM4(a1[1][0], a1[1][1], a1[1][2], a1[1][3], sA + aoff + 1280 + ka);
            LDSM4(a0[0][0], a0[0][1], a0[0][2], a0[0][3], sA + aoff + OFF_A0 + ka);
            LDSM4(a0[1][0], a0[1][1], a0[1][2], a0[1][3], sA + aoff + OFF_A0 + 1280 + ka);
            LDSM4(b1[0][0], b1[0][1], b1[1][0], b1[1][1], sA + boff + ka);
            LDSM4(b1[2][0], b1[2][1], b1[3][0], b1[3][1], sA + boff + 1280 + ka);
            LDSM2(b1[4][0], b1[4][1], sA + boff2 + ka);
            LDSM4(b0[0][0], b0[0][1], b0[1][0], b0[1][1], sA + boff + 6400 + ka);
            LDSM4(b0[2][0], b0[2][1], b0[3][0], b0[3][1], sA + boff + 6400 + 1280 + ka);
            LDSM2(b0[4][0], b0[4][1], sA + boff2 + 6400 + ka);

            #pragma unroll
            for (int im = 0; im < 2; im++)
                #pragma unroll
                for (int in = 0; in < 5; in++) {
                    mma_s8(accH[im][in], a1[im], b1[in]);
                    mma_s8(accM[im][in], a1[im], b0[in]);
                    mma_s8(accM[im][in], a0[im], b1[in]);
                }
        }
    }

    const size_t outBase = (size_t)z * BATCH * HID;
    #pragma unroll
    for (int im = 0; im < 2; im++) {
        #pragma unroll
        for (int in = 0; in < 5; in++) {
            int row = mbase + wm + im * 16 + grp;
            int col = nbase + wn + in * 8 + qd * 2;
            size_t o = outBase + (size_t)row * HID + col;
            *(int2*)(ph + o) = make_int2(accH[im][in][0], accH[im][in][1]);
            *(int2*)(ph + o + 8 * HID) = make_int2(accH[im][in][2], accH[im][in][3]);
            *(int2*)(pm + o) = make_int2(accM[im][in][0], accM[im][in][1]);
            *(int2*)(pm + o + 8 * HID) = make_int2(accM[im][in][2], accM[im][in][3]);
        }
    }
}

// =====================================================================
// reduce split-K partials -> h0 (dequant + bias), fused BN partials
// =====================================================================
__global__ __launch_bounds__(256) void reduce_h0_stats(
    const int* __restrict__ ph, const int* __restrict__ pm,
    const float* __restrict__ ascale, const float* __restrict__ bscale,
    const float* __restrict__ bias, float* __restrict__ h0,
    float* __restrict__ pstat)
{
    const int blk = blockIdx.x;          // 0..NB-1, 8 rows each
    const int t = threadIdx.x;
    const int r0 = blk * (BATCH / NB);
    const int c0 = t, c1 = t + 256;
    const float bs0 = bscale[c0];
    const float bi0 = bias[c0];
    float bs1 = 0.f, bi1 = 0.f;
    if (c1 < HID) { bs1 = bscale[c1]; bi1 = bias[c1]; }

    float s0 = 0.f, q0 = 0.f, s1 = 0.f, q1 = 0.f;
    for (int r = 0; r < BATCH / NB; r++) {
        const int row = r0 + r;
        const float as = ascale[row];
        size_t base = (size_t)row * HID;
        {
            int Ph = 0, Pm = 0;
            #pragma unroll
            for (int zz = 0; zz < KSPLIT0; zz++) {
                Ph += ph[(size_t)zz * BATCH * HID + base + c0];
                Pm += pm[(size_t)zz * BATCH * HID + base + c0];
            }
            float v = fmaf(as * bs0, 65536.0f * (float)Ph + 256.0f * (float)Pm, bi0);
            h0[base + c0] = v; s0 += v; q0 += v * v;
        }
        if (c1 < HID) {
            int Ph = 0, Pm = 0;
            #pragma unroll
            for (int zz = 0; zz < KSPLIT0; zz++) {
                Ph += ph[(size_t)zz * BATCH * HID + base + c1];
                Pm += pm[(size_t)zz * BATCH * HID + base + c1];
            }
            float v = fmaf(as * bs1, 65536.0f * (float)Ph + 256.0f * (float)Pm, bi1);
            h0[base + c1] = v; s1 += v; q1 += v * v;
        }
    }
    pstat[c0 * NB + blk] = s0; pstat[SQOFF + c0 * NB + blk] = q0;
    if (c1 < HID) { pstat[c1 * NB + blk] = s1; pstat[SQOFF + c1 * NB + blk] = q1; }
}

// =====================================================================
// BN pass1 on an h buffer
// =====================================================================
__global__ __launch_bounds__(256) void bn_pass1(
    const float* __restrict__ h, float* __restrict__ pstat)
{
    const int blk = blockIdx.x;
    const int t = threadIdx.x;
    const int r0 = blk * (BATCH / NB);
    const int c0 = t, c1 = t + 256;
    float s0 = 0.f, q0 = 0.f, s1 = 0.f, q1 = 0.f;
    for (int r = 0; r < BATCH / NB; r++) {
        size_t base = (size_t)(r0 + r) * HID;
        float v = h[base + c0]; s0 += v; q0 += v * v;
        if (c1 < HID) { float w = h[base + c1]; s1 += w; q1 += w * w; }
    }
    pstat[c0 * NB + blk] = s0; pstat[SQOFF + c0 * NB + blk] = q0;
    if (c1 < HID) { pstat[c1 * NB + blk] = s1; pstat[SQOFF + c1 * NB + blk] = q1; }
}

// =====================================================================
// BN finalize
// =====================================================================
__global__ __launch_bounds__(128) void stats_fin(
    const float* __restrict__ pstat, const float* __restrict__ g,
    const float* __restrict__ be, float* __restrict__ sc, float* __restrict__ sh)
{
    __shared__ float ss[128], sq[128];
    const int c = blockIdx.x, t = threadIdx.x;
    float s = 0.f, q = 0.f;
    for (int i = t; i < NB; i += 128) {
        s += pstat[c * NB + i];
        q += pstat[SQOFF + c * NB + i];
    }
    ss[t] = s; sq[t] = q;
    __syncthreads();
    for (int o = 64; o > 0; o >>= 1) {
        if (t < o) { ss[t] += ss[t + o]; sq[t] += sq[t + o]; }
        __syncthreads();
    }
    if (t == 0) {
        double mu = (double)ss[0] / BATCH;
        double var = (double)sq[0] / BATCH - mu * mu;
        if (var < 0.0) var = 0.0;
        float rstd = (float)(1.0 / sqrt(var + (double)EPS));
        float scv = g[c] * rstd;
        sc[c] = scv;
        sh[c] = be[c] - (float)mu * scv;
    }
}

// =====================================================================
// gemm_bf3 (small layers): bf16 3-product, CTA 128x80, BK=32
// =====================================================================
__global__ __launch_bounds__(256, 1) void gemm_bf3(
    const __nv_bfloat16* __restrict__ aH, const __nv_bfloat16* __restrict__ aL,
    const __nv_bfloat16* __restrict__ bH, const __nv_bfloat16* __restrict__ bL,
    float* __restrict__ out, const float* __restrict__ bias, int Kst)
{
    extern __shared__ char smem[];
    const uint32_t sb = smem_u32(smem);
    const int tid  = threadIdx.x;
    const int wid  = tid >> 5;
    const int lane = tid & 31;

    const int nbase = blockIdx.x * BN;
    const int mbase = blockIdx.y * BM;
    const int T = Kst / 32;

    const int wm = (wid & 3) * 32;
    const int wn = (wid >> 2) * 40;
    const int grp = lane >> 2;
    const int qd  = lane & 3;

    const uint32_t aoff = (uint32_t)((wm + (lane & 15)) * A_ROWB + ((lane >> 4) * 16));
    const int rowB = (lane & 7) + ((lane >> 4) << 3);
    const int kB   = ((lane >> 3) & 1) * 16;
    const uint32_t boff  = (uint32_t)(OFF_B1 + (wn + rowB) * A_ROWB + kB);
    const uint32_t boff2 = (uint32_t)(OFF_B1 + (wn + 32 + (lane & 7)) * A_ROWB + kB);

    float acc[2][5][4];
    #pragma unroll
    for (int im = 0; im < 2; im++)
        #pragma unroll
        for (int in = 0; in < 5; in++)
            #pragma unroll
            for (int r = 0; r < 4; r++) acc[im][in][r] = 0.0f;

    auto load_tile = [&](int s, int t) {
        const int k0 = t * 32;
        const uint32_t st = sb + s * STAGE;
        #pragma unroll
        for (int i = 0; i < 2; i++) {
            int idx = tid + i * 256;
            int rr = idx >> 2, ch = idx & 3;
            uint32_t dst = st + rr * A_ROWB + ch * 16;
            size_t g = (size_t)(mbase + rr) * Kst + k0 + ch * 8;
            CP_ASYNC16(dst, aH + g);
            CP_ASYNC16(dst + OFF_A0, aL + g);
        }
        if (tid < 320) {
            int rr = tid >> 2, ch = tid & 3;
            uint32_t dst = st + OFF_B1 + rr * A_ROWB + ch * 16;
            size_t g = (size_t)(nbase + rr) * Kst + k0 + ch * 8;
            CP_ASYNC16(dst, bH + g);
            CP_ASYNC16(dst + 6400, bL + g);
        }
        if (tid < 64) {
            int idx = tid + 256;
            int rr = idx >> 2, ch = idx & 3;
            uint32_t dst = st + OFF_B1 + rr * A_ROWB + ch * 16;
            size_t g = (size_t)(nbase + rr) * Kst + k0 + ch * 8;
            CP_ASYNC16(dst, bH + g);
            CP_ASYNC16(dst + 6400, bL + g);
        }
        CP_COMMIT();
    };

    load_tile(0, 0);
    load_tile(1, 1);
    load_tile(2, 2);

    for (int u = 0; u < T; ++u) {
        const int rem = T - 1 - u;
        if (rem >= 2) { CP_WAIT2(); } else if (rem == 1) { CP_WAIT1(); } else { CP_WAIT0(); }
        __syncthreads();

        if (u + 3 < T) load_tile((u + 3) & 3, u + 3);

        const uint32_t sA = sb + (u & 3) * STAGE;
        #pragma unroll
        for (int ks = 0; ks < 2; ks++) {
            const uint32_t ka = ks * 32;
            uint32_t ah[2][4], al[2][4], bh[5][2], bl[5][2];
            LDSM4(ah[0][0], ah[0][1], ah[0][2], ah[0][3], sA + aoff + ka);
            LDSM4(ah[1][0], ah[1][1], ah[1][2], ah[1][3], sA + aoff + 1280 + ka);
            LDSM4(al[0][0], al[0][1], al[0][2], al[0][3], sA + aoff + OFF_A0 + ka);
            LDSM4(al[1][0], al[1][1], al[1][2], al[1][3], sA + aoff + OFF_A0 + 1280 + ka);
            LDSM4(bh[0][0], bh[0][1], bh[1][0], bh[1][1], sA + boff + ka);
            LDSM4(bh[2][0], bh[2][1], bh[3][0], bh[3][1], sA + boff + 1280 + ka);
            LDSM2(bh[4][0], bh[4][1], sA + boff2 + ka);
            LDSM4(bl[0][0], bl[0][1], bl[1][0], bl[1][1], sA + boff + 6400 + ka);
            LDSM4(bl[2][0], bl[2][1], bl[3][0], bl[3][1], sA + boff + 6400 + 1280 + ka);
            LDSM2(bl[4][0], bl[4][1], sA + boff2 + 6400 + ka);

            #pragma unroll
            for (int im = 0; im < 2; im++)
                #pragma unroll
                for (int in = 0; in < 5; in++) {
                    mma_bf16(acc[im][in], ah[im], bh[in]);
                    mma_bf16(acc[im][in], ah[im], bl[in]);
                    mma_bf16(acc[im][in], al[im], bh[in]);
                }
        }
    }

    #pragma unroll
    for (int im = 0; im < 2; im++) {
        #pragma unroll
        for (int in = 0; in < 5; in++) {
            int row = mbase + wm + im * 16 + grp;
            int col = nbase + wn + in * 8 + qd * 2;
            float b0v = bias[col], b1v = bias[col + 1];
            float* d = out + (size_t)row * HID + col;
            *(float2*)d = make_float2(acc[im][in][0] + b0v, acc[im][in][1] + b1v);
            *(float2*)(d + 8 * HID) = make_float2(acc[im][in][2] + b0v, acc[im][in][3] + b1v);
        }
    }
}

// =====================================================================
// conv_split / wsplit (bf16 hi/lo for small layers)
// =====================================================================
__global__ __launch_bounds__(256) void conv_split(
    const float* __restrict__ h, const float* __restrict__ sc,
    const float* __restrict__ sh,
    __nv_bfloat16* __restrict__ hi, __nv_bfloat16* __restrict__ lo)
{
    int idx = blockIdx.x * 256 + threadIdx.x;
    int row = idx / K2P, col = idx - row * K2P;
    float v = 0.0f;
    if (col < HID)
        v = fmaxf(h[(size_t)row * HID + col] * sc[col] + sh[col], 0.0f);
    __nv_bfloat16 hh = __float2bfloat16(v);
    hi[idx] = hh;
    lo[idx] = __float2bfloat16(v - __bfloat162float(hh));
}

__global__ __launch_bounds__(256) void wsplit(
    const float* __restrict__ w, __nv_bfloat16* __restrict__ hi,
    __nv_bfloat16* __restrict__ lo)
{
    int idx = blockIdx.x * 256 + threadIdx.x;
    int row = idx / K2P, col = idx - row * K2P;
    float v = (col < HID) ? w[row * HID + col] : 0.0f;
    __nv_bfloat16 h = __float2bfloat16(v);
    hi[idx] = h;
    lo[idx] = __float2bfloat16(v - __bfloat162float(h));
}

// =====================================================================
// final dot
// =====================================================================
__global__ __launch_bounds__(256) void final_dot(
    const float* __restrict__ h, const float* __restrict__ scale,
    const float* __restrict__ shift, const float* __restrict__ w3,
    const float* __restrict__ b3, float* __restrict__ out)
{
    const int gtid = blockIdx.x * blockDim.x + threadIdx.x;
    const int warp = gtid >> 5;
    const int lane = gtid & 31;
    if (warp >= BATCH) return;
    float s = 0.0f;
    for (int k = lane; k < HID; k += 32) {
        float v = fmaxf(h[(size_t)warp * HID + k] * scale[k] + shift[k], 0.0f);
        s += v * w3[k];
    }
    #pragma unroll
    for (int off = 16; off > 0; off >>= 1)
        s += __shfl_down_sync(0xFFFFFFFFu, s, off);
    if (lane == 0) out[warp] = s + b3[0];
}

// =====================================================================
// launcher
// =====================================================================
extern "C" void kernel_launch(void* const* d_in, const int* in_sizes, int n_in,
                              void* d_out, int out_size)
{
    const int*   x    = (const int*)  d_in[0];
    const float* emb  = (const float*)d_in[1];
    const float* sw1  = (const float*)d_in[2];
    const float* sb1  = (const float*)d_in[3];
    const float* sw2  = (const float*)d_in[4];
    const float* sb2  = (const float*)d_in[5];
    const float* Wb1  = (const float*)d_in[6];
    const float* Wb2  = (const float*)d_in[7];
    const float* mw0  = (const float*)d_in[8];
    const float* mb0  = (const float*)d_in[9];
    const float* g0   = (const float*)d_in[10];
    const float* be0  = (const float*)d_in[11];
    const float* mw1  = (const float*)d_in[12];
    const float* mb1  = (const float*)d_in[13];
    const float* g1   = (const float*)d_in[14];
    const float* be1  = (const float*)d_in[15];
    const float* mw2  = (const float*)d_in[16];
    const float* mb2  = (const float*)d_in[17];
    const float* g2   = (const float*)d_in[18];
    const float* be2  = (const float*)d_in[19];
    const float* mw3  = (const float*)d_in[20];
    const float* mb3  = (const float*)d_in[21];
    float* out = (float*)d_out;

    char *qa1, *qa0, *qb1, *qb0;
    int *ph, *pm;
    __nv_bfloat16 *a2_hi, *a2_lo, *w2_hi, *w2_lo;
    float *ascale, *bscale, *h0, *h1, *h2, *pstat, *sc, *sh;
    cudaGetSymbolAddress((void**)&qa1, d_qa1);
    cudaGetSymbolAddress((void**)&qa0, d_qa0);
    cudaGetSymbolAddress((void**)&qb1, d_qb1);
    cudaGetSymbolAddress((void**)&qb0, d_qb0);
    cudaGetSymbolAddress((void**)&ascale, d_ascale);
    cudaGetSymbolAddress((void**)&bscale, d_bscale);
    cudaGetSymbolAddress((void**)&ph, d_ph);
    cudaGetSymbolAddress((void**)&pm, d_pm);
    cudaGetSymbolAddress((void**)&a2_hi, d_a2_hi);
    cudaGetSymbolAddress((void**)&a2_lo, d_a2_lo);
    cudaGetSymbolAddress((void**)&w2_hi, d_w2_hi);
    cudaGetSymbolAddress((void**)&w2_lo, d_w2_lo);
    cudaGetSymbolAddress((void**)&h0, d_h0);
    cudaGetSymbolAddress((void**)&h1, d_h1);
    cudaGetSymbolAddress((void**)&h2, d_h2);
    cudaGetSymbolAddress((void**)&pstat, d_pstat);
    cudaGetSymbolAddress((void**)&sc, d_scale);
    cudaGetSymbolAddress((void**)&sh, d_shift);

    static int smem_set = 0;
    if (!smem_set) {
        cudaFuncSetAttribute(gemm0_i8, cudaFuncAttributeMaxDynamicSharedMemorySize, SMEM_G);
        cudaFuncSetAttribute(gemm_bf3, cudaFuncAttributeMaxDynamicSharedMemorySize, SMEM_G);
        smem_set = 1;
    }

    // 1) front end -> int8 pair A; quantize mw0
    fuse_front<<<BATCH, 256>>>(x, emb, sw1, sb1, sw2, sb2, Wb1, Wb2, qa1, qa0, ascale);
    quant_b<<<HID, 256>>>(mw0, qb1, qb0, bscale);

    // 2) GEMM0 int8 (split-K=8) + fused dequant/reduce/BN-partials
    {
        dim3 grid(HID / BN, BATCH / BM, KSPLIT0);   // (5, 32, 8)
        gemm0_i8<<<grid, 256, SMEM_G>>>(qa1, qa0, qb1, qb0, ph, pm, K1P, KSPLIT0);
        reduce_h0_stats<<<NB, 256>>>(ph, pm, ascale, bscale, mb0, h0, pstat);
        stats_fin<<<HID, 128>>>(pstat, g0, be0, sc + 0 * HID, sh + 0 * HID);
    }

    // 3) layer 1
    conv_split<<<BATCH * K2P / 256, 256>>>(h0, sc + 0 * HID, sh + 0 * HID, a2_hi, a2_lo);
    wsplit<<<HID * K2P / 256, 256>>>(mw1, w2_hi, w2_lo);
    {
        dim3 grid(HID / BN, BATCH / BM, 1);
        gemm_bf3<<<grid, 256, SMEM_G>>>(a2_hi, a2_lo, w2_hi, w2_lo, h1, mb1, K2P);
    }
    bn_pass1<<<NB, 256>>>(h1, pstat);
    stats_fin<<<HID, 128>>>(pstat, g1, be1, sc + 1 * HID, sh + 1 * HID);

    // 4) layer 2
    conv_split<<<BATCH * K2P / 256, 256>>>(h1, sc + 1 * HID, sh + 1 * HID, a2_hi, a2_lo);
    wsplit<<<HID * K2P / 256, 256>>>(mw2, w2_hi, w2_lo);
    {
        dim3 grid(HID / BN, BATCH / BM, 1);
        gemm_bf3<<<grid, 256, SMEM_G>>>(a2_hi, a2_lo, w2_hi, w2_lo, h2, mb2, K2P);
    }
    bn_pass1<<<NB, 256>>>(h2, pstat);
    stats_fin<<<HID, 128>>>(pstat, g2, be2, sc + 2 * HID, sh + 2 * HID);

    // 5) final dot
    final_dot<<<(BATCH * 32 + 255) / 256, 256>>>(h2, sc + 2 * HID, sh + 2 * HID,
                                                 mw3, mb3, out);
}

// round 7
// speedup vs baseline: 1.9951x; 1.9951x over previous
#include <cuda_runtime.h>
#include <cuda_bf16.h>
#include <math.h>
#include <stdint.h>

// ---------------- problem constants ----------------
#define BATCH 4096
#define NF    39
#define NE    16
#define NPAIR 741
#define K1    (2 * NPAIR * NE)    // 23712
#define HID   400
#define K2P   416                 // HID padded for small layers
#define EPS   1e-5f

// ---------------- GEMM0: BM=64 x BN=400, BK=32 halves, 3-stage ----------------
#define G0_BM   64
#define G0_ROWB 80                // smem row stride (32 halves + pad)
#define G0_AHI  0
#define G0_ALO  5120              // 64*80
#define G0_BHI  10240
#define G0_BLO  42240             // +400*80
#define G0_STAGE 74240
#define G0_SMEM  (G0_STAGE * 3)   // 222720
#define KSPLIT0 16
#define G0_TILES 741              // K1/32

// ---------------- small-layer GEMM tiling (R5 config) ----------------
#define BM 128
#define BN 80
#define A_ROWB 80
#define OFF_A0  10240
#define OFF_B1  20480
#define STAGE   33280
#define SMEM_G  (STAGE * 4)       // 133120

#define NB      512               // stat partial blocks
#define SQOFF   (HID * NB)

// ---------------- scratch ----------------
__device__ __nv_bfloat16 d_a_hi[(size_t)BATCH * K1];
__device__ __nv_bfloat16 d_a_lo[(size_t)BATCH * K1];
__device__ __nv_bfloat16 d_b_hi[(size_t)HID * K1];
__device__ __nv_bfloat16 d_b_lo[(size_t)HID * K1];
__device__ float d_part[(size_t)KSPLIT0 * BATCH * HID];   // 105 MB
__device__ __nv_bfloat16 d_a2_hi[(size_t)BATCH * K2P];
__device__ __nv_bfloat16 d_a2_lo[(size_t)BATCH * K2P];
__device__ __nv_bfloat16 d_w2_hi[(size_t)HID * K2P];
__device__ __nv_bfloat16 d_w2_lo[(size_t)HID * K2P];
__device__ float d_h0[BATCH * HID];
__device__ float d_h1[BATCH * HID];
__device__ float d_h2[BATCH * HID];
__device__ float d_pstat[2 * NB * HID];
__device__ float d_scale[3][HID];
__device__ float d_shift[3][HID];

// ---------------- helpers ----------------
__device__ __forceinline__ uint32_t smem_u32(const void* p) {
    uint32_t a;
    asm("{ .reg .u64 t; cvta.to.shared.u64 t, %1; cvt.u32.u64 %0, t; }" : "=r"(a) : "l"(p));
    return a;
}

#define CP_ASYNC16(dst, src) \
    asm volatile("cp.async.cg.shared.global [%0], [%1], 16;" :: "r"(dst), "l"(src))
#define CP_COMMIT() asm volatile("cp.async.commit_group;" ::: "memory")
#define CP_WAIT2()  asm volatile("cp.async.wait_group 2;" ::: "memory")
#define CP_WAIT1()  asm volatile("cp.async.wait_group 1;" ::: "memory")
#define CP_WAIT0()  asm volatile("cp.async.wait_group 0;" ::: "memory")

#define LDSM4(r0, r1, r2, r3, a) \
    asm volatile("ldmatrix.sync.aligned.m8n8.x4.shared.b16 {%0,%1,%2,%3}, [%4];" \
        : "=r"(r0), "=r"(r1), "=r"(r2), "=r"(r3) : "r"(a))
#define LDSM2(r0, r1, a) \
    asm volatile("ldmatrix.sync.aligned.m8n8.x2.shared.b16 {%0,%1}, [%2];" \
        : "=r"(r0), "=r"(r1) : "r"(a))

__device__ __forceinline__ void mma_bf16(float* c, const uint32_t* a, const uint32_t* b) {
    asm volatile(
        "mma.sync.aligned.m16n8k16.row.col.f32.bf16.bf16.f32 "
        "{%0,%1,%2,%3}, {%4,%5,%6,%7}, {%8,%9}, {%0,%1,%2,%3};"
        : "+f"(c[0]), "+f"(c[1]), "+f"(c[2]), "+f"(c[3])
        : "r"(a[0]), "r"(a[1]), "r"(a[2]), "r"(a[3]), "r"(b[0]), "r"(b[1]));
}

// =====================================================================
// Kernel 1: gather + SENET + bilinear -> A_hi / A_lo (bf16 split)
// =====================================================================
__global__ __launch_bounds__(256) void fuse_front(
    const int* __restrict__ x,
    const float* __restrict__ emb,
    const float* __restrict__ w1, const float* __restrict__ b1,
    const float* __restrict__ w2, const float* __restrict__ b2,
    const float* __restrict__ Wb1, const float* __restrict__ Wb2,
    __nv_bfloat16* __restrict__ a_hi, __nv_bfloat16* __restrict__ a_lo)
{
    __shared__ float xe[NF][NE];
    __shared__ float xs[NF][NE];
    __shared__ float p1[NF][NE];
    __shared__ float p2[NF][NE];
    __shared__ float zf[NF], av[NF], af[NF];
    __shared__ unsigned char ii[NPAIR], jj[NPAIR];
    __shared__ int is64;

    const int b = blockIdx.x;
    const int tid = threadIdx.x;

    if (tid == 0) {
        int f64 = 1;
        for (int w = 1; w < 2 * NF; w += 2)
            if (x[w] != 0) { f64 = 0; break; }
        is64 = f64;
    }
    for (int k = tid; k < NPAIR; k += 256) {
        int i = 0, rem = k;
        while (rem >= NF - 1 - i) { rem -= NF - 1 - i; i++; }
        ii[k] = (unsigned char)i;
        jj[k] = (unsigned char)(i + 1 + rem);
    }
    __syncthreads();

    for (int idx = tid; idx < NF * NE; idx += 256) {
        int f = idx >> 4, e = idx & 15;
        int xv = is64 ? x[2 * (b * NF + f)] : x[b * NF + f];
        xe[f][e] = emb[(xv + 1000 * f) * NE + e];
    }
    __syncthreads();

    if (tid < NF) {
        float m = xe[tid][0];
        #pragma unroll
        for (int e = 1; e < NE; e++) m = fmaxf(m, xe[tid][e]);
        zf[tid] = m;
    }
    __syncthreads();
    if (tid < NF) {
        float s = b1[tid];
        for (int j = 0; j < NF; j++) s += zf[j] * w1[tid * NF + j];
        av[tid] = fmaxf(s, 0.0f);
    }
    __syncthreads();
    if (tid < NF) {
        float s = b2[tid];
        for (int j = 0; j < NF; j++) s += av[j] * w2[tid * NF + j];
        af[tid] = fmaxf(s, 0.0f);
    }
    __syncthreads();

    for (int idx = tid; idx < NF * NE; idx += 256) {
        int f = idx >> 4, d = idx & 15;
        float s1 = 0.0f, s2 = 0.0f;
        #pragma unroll
        for (int e = 0; e < NE; e++) {
            float v = xe[f][e];
            s1 += v * Wb1[d * NE + e];
            s2 += v * Wb2[d * NE + e];
        }
        p1[f][d] = s1;
        p2[f][d] = af[f] * s2;
        xs[f][d] = af[f] * xe[f][d];
    }
    __syncthreads();

    __nv_bfloat16* ohi = a_hi + (size_t)b * K1;
    __nv_bfloat16* olo = a_lo + (size_t)b * K1;
    for (int idx = tid; idx < NPAIR * NE; idx += 256) {
        int k = idx >> 4, e = idx & 15;
        int i = ii[k], j = jj[k];
        float v1 = p1[i][e] * xe[j][e];
        float v2 = p2[i][e] * xs[j][e];
        __nv_bfloat16 h1 = __float2bfloat16(v1);
        __nv_bfloat16 h2 = __float2bfloat16(v2);
        ohi[idx] = h1;
        olo[idx] = __float2bfloat16(v1 - __bfloat162float(h1));
        ohi[idx + NPAIR * NE] = h2;
        olo[idx + NPAIR * NE] = __float2bfloat16(v2 - __bfloat162float(h2));
    }
}

// =====================================================================
// Kernel 1b: split mw0 into bf16 hi/lo
// =====================================================================
__global__ __launch_bounds__(256) void split_b(
    const float* __restrict__ w, __nv_bfloat16* __restrict__ hi,
    __nv_bfloat16* __restrict__ lo)
{
    size_t i = (size_t)blockIdx.x * 256 + threadIdx.x;
    size_t n = (size_t)HID * K1;
    if (i < n) {
        float v = w[i];
        __nv_bfloat16 h = __float2bfloat16(v);
        hi[i] = h;
        lo[i] = __float2bfloat16(v - __bfloat162float(h));
    }
}

// =====================================================================
// Kernel 2: GEMM0 bf16 3-product, full-N CTA (BM=64 x BN=400), split-K=16
//   part[z][m,n] = sum_{k in seg z} A[m,k]*B[n,k]
//   8 warps (4m x 2n), warp tile 16 x 200, B in five 40-col chunks
// =====================================================================
__global__ __launch_bounds__(256, 1) void gemm0_bf3w(
    const __nv_bfloat16* __restrict__ aH, const __nv_bfloat16* __restrict__ aL,
    const __nv_bfloat16* __restrict__ bH, const __nv_bfloat16* __restrict__ bL,
    float* __restrict__ part)
{
    extern __shared__ char smem[];
    const uint32_t sb = smem_u32(smem);
    const int tid  = threadIdx.x;
    const int wid  = tid >> 5;
    const int lane = tid & 31;

    const int mbase = blockIdx.x * G0_BM;
    const int z     = blockIdx.y;

    const int qt = G0_TILES / KSPLIT0, rt = G0_TILES % KSPLIT0;   // 46, 5
    const int t0 = z * qt + (z < rt ? z : rt);
    const int T  = qt + (z < rt ? 1 : 0);

    const int wm = (wid & 3) * 16;    // warp m origin (0,16,32,48)
    const int wn = (wid >> 2) * 200;  // warp n origin (0,200)
    const int grp = lane >> 2;
    const int qd  = lane & 3;

    // A frag base: 16 rows x 16B columns
    const uint32_t aoff = (uint32_t)(G0_AHI + (wm + (lane & 15)) * G0_ROWB + ((lane >> 4) * 16));
    const int rowB = (lane & 7) + ((lane >> 4) << 3);
    const int kB   = ((lane >> 3) & 1) * 16;

    float acc[5][5][4];
    #pragma unroll
    for (int c = 0; c < 5; c++)
        #pragma unroll
        for (int f = 0; f < 5; f++)
            #pragma unroll
            for (int r = 0; r < 4; r++) acc[c][f][r] = 0.0f;

    auto load_tile = [&](int s, int t) {
        const int k0 = t * 32;
        const uint32_t st = sb + s * G0_STAGE;
        {   // A: 64 rows x 4 chunks = 256 (exactly one per thread)
            int rr = tid >> 2, ch = tid & 3;
            uint32_t dst = st + G0_AHI + rr * G0_ROWB + ch * 16;
            size_t g = (size_t)(mbase + rr) * K1 + k0 + ch * 8;
            CP_ASYNC16(dst, aH + g);
            CP_ASYNC16(dst + (G0_ALO - G0_AHI), aL + g);
        }
        // B: 400 rows x 4 chunks = 1600
        #pragma unroll
        for (int i = 0; i < 7; i++) {
            int idx = tid + i * 256;
            if (idx < 1600) {
                int rr = idx >> 2, ch = idx & 3;
                uint32_t dst = st + G0_BHI + rr * G0_ROWB + ch * 16;
                size_t g = (size_t)rr * K1 + k0 + ch * 8;
                CP_ASYNC16(dst, bH + g);
                CP_ASYNC16(dst + (G0_BLO - G0_BHI), bL + g);
            }
        }
        CP_COMMIT();
    };

    // prologue: depth-2 prefetch over 3 buffers (T >= 46)
    load_tile(0, t0);
    load_tile(1, t0 + 1);

    for (int u = 0; u < T; ++u) {
        if (u < T - 1) { CP_WAIT1(); } else { CP_WAIT0(); }
        __syncthreads();

        if (u + 2 < T) load_tile((u + 2) % 3, t0 + u + 2);

        const uint32_t sA = sb + (u % 3) * G0_STAGE;
        #pragma unroll
        for (int ks = 0; ks < 2; ks++) {
            const uint32_t ka = ks * 32;
            uint32_t ah[4], al[4];
            LDSM4(ah[0], ah[1], ah[2], ah[3], sA + aoff + ka);
            LDSM4(al[0], al[1], al[2], al[3], sA + aoff + (G0_ALO - G0_AHI) + ka);

            #pragma unroll
            for (int c = 0; c < 5; c++) {
                const uint32_t boff  = sA + G0_BHI + (wn + c * 40 + rowB) * G0_ROWB + kB + ka;
                const uint32_t boff2 = sA + G0_BHI + (wn + c * 40 + 32 + (lane & 7)) * G0_ROWB + kB + ka;
                uint32_t bh[5][2], bl[5][2];
                LDSM4(bh[0][0], bh[0][1], bh[1][0], bh[1][1], boff);
                LDSM4(bh[2][0], bh[2][1], bh[3][0], bh[3][1], boff + 8 * G0_ROWB * 2);
                LDSM2(bh[4][0], bh[4][1], boff2);
                LDSM4(bl[0][0], bl[0][1], bl[1][0], bl[1][1], boff + (G0_BLO - G0_BHI));
                LDSM4(bl[2][0], bl[2][1], bl[3][0], bl[3][1], boff + (G0_BLO - G0_BHI) + 8 * G0_ROWB * 2);
                LDSM2(bl[4][0], bl[4][1], boff2 + (G0_BLO - G0_BHI));

                #pragma unroll
                for (int f = 0; f < 5; f++) {
                    mma_bf16(acc[c][f], ah, bh[f]);
                    mma_bf16(acc[c][f], ah, bl[f]);
                    mma_bf16(acc[c][f], al, bh[f]);
                }
            }
        }
    }

    // epilogue: fp32 partials
    const size_t outBase = (size_t)z * BATCH * HID;
    #pragma unroll
    for (int c = 0; c < 5; c++) {
        #pragma unroll
        for (int f = 0; f < 5; f++) {
            int row = mbase + wm + grp;
            int col = wn + c * 40 + f * 8 + qd * 2;
            float* d = part + outBase + (size_t)row * HID + col;
            *(float2*)d = make_float2(acc[c][f][0], acc[c][f][1]);
            *(float2*)(d + 8 * HID) = make_float2(acc[c][f][2], acc[c][f][3]);
        }
    }
}

// =====================================================================
// reduce split-K partials + bias -> h0, fused BN partials
// =====================================================================
__global__ __launch_bounds__(256) void reduce_h0_stats(
    const float* __restrict__ part, const float* __restrict__ bias,
    float* __restrict__ h0, float* __restrict__ pstat)
{
    const int blk = blockIdx.x;          // 0..NB-1, BATCH/NB rows each
    const int t = threadIdx.x;
    const int r0 = blk * (BATCH / NB);
    const int c0 = t, c1 = t + 256;
    const float bi0 = bias[c0];
    float bi1 = 0.f;
    if (c1 < HID) bi1 = bias[c1];

    float s0 = 0.f, q0 = 0.f, s1 = 0.f, q1 = 0.f;
    for (int r = 0; r < BATCH / NB; r++) {
        size_t base = (size_t)(r0 + r) * HID;
        {
            float v = bi0;
            #pragma unroll
            for (int zz = 0; zz < KSPLIT0; zz++)
                v += part[(size_t)zz * BATCH * HID + base + c0];
            h0[base + c0] = v; s0 += v; q0 += v * v;
        }
        if (c1 < HID) {
            float v = bi1;
            #pragma unroll
            for (int zz = 0; zz < KSPLIT0; zz++)
                v += part[(size_t)zz * BATCH * HID + base + c1];
            h0[base + c1] = v; s1 += v; q1 += v * v;
        }
    }
    pstat[c0 * NB + blk] = s0; pstat[SQOFF + c0 * NB + blk] = q0;
    if (c1 < HID) { pstat[c1 * NB + blk] = s1; pstat[SQOFF + c1 * NB + blk] = q1; }
}

// =====================================================================
// BN pass1 / finalize
// =====================================================================
__global__ __launch_bounds__(256) void bn_pass1(
    const float* __restrict__ h, float* __restrict__ pstat)
{
    const int blk = blockIdx.x;
    const int t = threadIdx.x;
    const int r0 = blk * (BATCH / NB);
    const int c0 = t, c1 = t + 256;
    float s0 = 0.f, q0 = 0.f, s1 = 0.f, q1 = 0.f;
    for (int r = 0; r < BATCH / NB; r++) {
        size_t base = (size_t)(r0 + r) * HID;
        float v = h[base + c0]; s0 += v; q0 += v * v;
        if (c1 < HID) { float w = h[base + c1]; s1 += w; q1 += w * w; }
    }
    pstat[c0 * NB + blk] = s0; pstat[SQOFF + c0 * NB + blk] = q0;
    if (c1 < HID) { pstat[c1 * NB + blk] = s1; pstat[SQOFF + c1 * NB + blk] = q1; }
}

__global__ __launch_bounds__(128) void stats_fin(
    const float* __restrict__ pstat, const float* __restrict__ g,
    const float* __restrict__ be, float* __restrict__ sc, float* __restrict__ sh)
{
    __shared__ float ss[128], sq[128];
    const int c = blockIdx.x, t = threadIdx.x;
    float s = 0.f, q = 0.f;
    for (int i = t; i < NB; i += 128) {
        s += pstat[c * NB + i];
        q += pstat[SQOFF + c * NB + i];
    }
    ss[t] = s; sq[t] = q;
    __syncthreads();
    for (int o = 64; o > 0; o >>= 1) {
        if (t < o) { ss[t] += ss[t + o]; sq[t] += sq[t + o]; }
        __syncthreads();
    }
    if (t == 0) {
        double mu = (double)ss[0] / BATCH;
        double var = (double)sq[0] / BATCH - mu * mu;
        if (var < 0.0) var = 0.0;
        float rstd = (float)(1.0 / sqrt(var + (double)EPS));
        float scv = g[c] * rstd;
        sc[c] = scv;
        sh[c] = be[c] - (float)mu * scv;
    }
}

// =====================================================================
// gemm_bf3 (small layers): bf16 3-product, CTA 128x80, BK=32, 4 stages
// =====================================================================
__global__ __launch_bounds__(256, 1) void gemm_bf3(
    const __nv_bfloat16* __restrict__ aH, const __nv_bfloat16* __restrict__ aL,
    const __nv_bfloat16* __restrict__ bH, const __nv_bfloat16* __restrict__ bL,
    float* __restrict__ out, const float* __restrict__ bias, int Kst)
{
    extern __shared__ char smem[];
    const uint32_t sb = smem_u32(smem);
    const int tid  = threadIdx.x;
    const int wid  = tid >> 5;
    const int lane = tid & 31;

    const int nbase = blockIdx.x * BN;
    const int mbase = blockIdx.y * BM;
    const int T = Kst / 32;

    const int wm = (wid & 3) * 32;
    const int wn = (wid >> 2) * 40;
    const int grp = lane >> 2;
    const int qd  = lane & 3;

    const uint32_t aoff = (uint32_t)((wm + (lane & 15)) * A_ROWB + ((lane >> 4) * 16));
    const int rowB = (lane & 7) + ((lane >> 4) << 3);
    const int kB   = ((lane >> 3) & 1) * 16;
    const uint32_t boff  = (uint32_t)(OFF_B1 + (wn + rowB) * A_ROWB + kB);
    const uint32_t boff2 = (uint32_t)(OFF_B1 + (wn + 32 + (lane & 7)) * A_ROWB + kB);

    float acc[2][5][4];
    #pragma unroll
    for (int im = 0; im < 2; im++)
        #pragma unroll
        for (int in = 0; in < 5; in++)
            #pragma unroll
            for (int r = 0; r < 4; r++) acc[im][in][r] = 0.0f;

    auto load_tile = [&](int s, int t) {
        const int k0 = t * 32;
        const uint32_t st = sb + s * STAGE;
        #pragma unroll
        for (int i = 0; i < 2; i++) {
            int idx = tid + i * 256;
            int rr = idx >> 2, ch = idx & 3;
            uint32_t dst = st + rr * A_ROWB + ch * 16;
            size_t g = (size_t)(mbase + rr) * Kst + k0 + ch * 8;
            CP_ASYNC16(dst, aH + g);
            CP_ASYNC16(dst + OFF_A0, aL + g);
        }
        if (tid < 320) {
            int rr = tid >> 2, ch = tid & 3;
            uint32_t dst = st + OFF_B1 + rr * A_ROWB + ch * 16;
            size_t g = (size_t)(nbase + rr) * Kst + k0 + ch * 8;
            CP_ASYNC16(dst, bH + g);
            CP_ASYNC16(dst + 6400, bL + g);
        }
        if (tid < 64) {
            int idx = tid + 256;
            int rr = idx >> 2, ch = idx & 3;
            uint32_t dst = st + OFF_B1 + rr * A_ROWB + ch * 16;
            size_t g = (size_t)(nbase + rr) * Kst + k0 + ch * 8;
            CP_ASYNC16(dst, bH + g);
            CP_ASYNC16(dst + 6400, bL + g);
        }
        CP_COMMIT();
    };

    load_tile(0, 0);
    load_tile(1, 1);
    load_tile(2, 2);

    for (int u = 0; u < T; ++u) {
        const int rem = T - 1 - u;
        if (rem >= 2) { CP_WAIT2(); } else if (rem == 1) { CP_WAIT1(); } else { CP_WAIT0(); }
        __syncthreads();

        if (u + 3 < T) load_tile((u + 3) & 3, u + 3);

        const uint32_t sA = sb + (u & 3) * STAGE;
        #pragma unroll
        for (int ks = 0; ks < 2; ks++) {
            const uint32_t ka = ks * 32;
            uint32_t ah[2][4], al[2][4], bh[5][2], bl[5][2];
            LDSM4(ah[0][0], ah[0][1], ah[0][2], ah[0][3], sA + aoff + ka);
            LDSM4(ah[1][0], ah[1][1], ah[1][2], ah[1][3], sA + aoff + 1280 + ka);
            LDSM4(al[0][0], al[0][1], al[0][2], al[0][3], sA + aoff + OFF_A0 + ka);
            LDSM4(al[1][0], al[1][1], al[1][2], al[1][3], sA + aoff + OFF_A0 + 1280 + ka);
            LDSM4(bh[0][0], bh[0][1], bh[1][0], bh[1][1], sA + boff + ka);
            LDSM4(bh[2][0], bh[2][1], bh[3][0], bh[3][1], sA + boff + 1280 + ka);
            LDSM2(bh[4][0], bh[4][1], sA + boff2 + ka);
            LDSM4(bl[0][0], bl[0][1], bl[1][0], bl[1][1], sA + boff + 6400 + ka);
            LDSM4(bl[2][0], bl[2][1], bl[3][0], bl[3][1], sA + boff + 6400 + 1280 + ka);
            LDSM2(bl[4][0], bl[4][1], sA + boff2 + 6400 + ka);

            #pragma unroll
            for (int im = 0; im < 2; im++)
                #pragma unroll
                for (int in = 0; in < 5; in++) {
                    mma_bf16(acc[im][in], ah[im], bh[in]);
                    mma_bf16(acc[im][in], ah[im], bl[in]);
                    mma_bf16(acc[im][in], al[im], bh[in]);
                }
        }
    }

    #pragma unroll
    for (int im = 0; im < 2; im++) {
        #pragma unroll
        for (int in = 0; in < 5; in++) {
            int row = mbase + wm + im * 16 + grp;
            int col = nbase + wn + in * 8 + qd * 2;
            float b0v = bias[col], b1v = bias[col + 1];
            float* d = out + (size_t)row * HID + col;
            *(float2*)d = make_float2(acc[im][in][0] + b0v, acc[im][in][1] + b1v);
            *(float2*)(d + 8 * HID) = make_float2(acc[im][in][2] + b0v, acc[im][in][3] + b1v);
        }
    }
}

// =====================================================================
// conv_split / wsplit
// =====================================================================
__global__ __launch_bounds__(256) void conv_split(
    const float* __restrict__ h, const float* __restrict__ sc,
    const float* __restrict__ sh,
    __nv_bfloat16* __restrict__ hi, __nv_bfloat16* __restrict__ lo)
{
    int idx = blockIdx.x * 256 + threadIdx.x;
    int row = idx / K2P, col = idx - row * K2P;
    float v = 0.0f;
    if (col < HID)
        v = fmaxf(h[(size_t)row * HID + col] * sc[col] + sh[col], 0.0f);
    __nv_bfloat16 hh = __float2bfloat16(v);
    hi[idx] = hh;
    lo[idx] = __float2bfloat16(v - __bfloat162float(hh));
}

__global__ __launch_bounds__(256) void wsplit(
    const float* __restrict__ w, __nv_bfloat16* __restrict__ hi,
    __nv_bfloat16* __restrict__ lo)
{
    int idx = blockIdx.x * 256 + threadIdx.x;
    int row = idx / K2P, col = idx - row * K2P;
    float v = (col < HID) ? w[row * HID + col] : 0.0f;
    __nv_bfloat16 h = __float2bfloat16(v);
    hi[idx] = h;
    lo[idx] = __float2bfloat16(v - __bfloat162float(h));
}

// =====================================================================
// final dot
// =====================================================================
__global__ __launch_bounds__(256) void final_dot(
    const float* __restrict__ h, const float* __restrict__ scale,
    const float* __restrict__ shift, const float* __restrict__ w3,
    const float* __restrict__ b3, float* __restrict__ out)
{
    const int gtid = blockIdx.x * blockDim.x + threadIdx.x;
    const int warp = gtid >> 5;
    const int lane = gtid & 31;
    if (warp >= BATCH) return;
    float s = 0.0f;
    for (int k = lane; k < HID; k += 32) {
        float v = fmaxf(h[(size_t)warp * HID + k] * scale[k] + shift[k], 0.0f);
        s += v * w3[k];
    }
    #pragma unroll
    for (int off = 16; off > 0; off >>= 1)
        s += __shfl_down_sync(0xFFFFFFFFu, s, off);
    if (lane == 0) out[warp] = s + b3[0];
}

// =====================================================================
// launcher
// =====================================================================
extern "C" void kernel_launch(void* const* d_in, const int* in_sizes, int n_in,
                              void* d_out, int out_size)
{
    const int*   x    = (const int*)  d_in[0];
    const float* emb  = (const float*)d_in[1];
    const float* sw1  = (const float*)d_in[2];
    const float* sb1  = (const float*)d_in[3];
    const float* sw2  = (const float*)d_in[4];
    const float* sb2  = (const float*)d_in[5];
    const float* Wb1  = (const float*)d_in[6];
    const float* Wb2  = (const float*)d_in[7];
    const float* mw0  = (const float*)d_in[8];
    const float* mb0  = (const float*)d_in[9];
    const float* g0   = (const float*)d_in[10];
    const float* be0  = (const float*)d_in[11];
    const float* mw1  = (const float*)d_in[12];
    const float* mb1  = (const float*)d_in[13];
    const float* g1   = (const float*)d_in[14];
    const float* be1  = (const float*)d_in[15];
    const float* mw2  = (const float*)d_in[16];
    const float* mb2  = (const float*)d_in[17];
    const float* g2   = (const float*)d_in[18];
    const float* be2  = (const float*)d_in[19];
    const float* mw3  = (const float*)d_in[20];
    const float* mb3  = (const float*)d_in[21];
    float* out = (float*)d_out;

    __nv_bfloat16 *a_hi, *a_lo, *b_hi, *b_lo, *a2_hi, *a2_lo, *w2_hi, *w2_lo;
    float *part, *h0, *h1, *h2, *pstat, *sc, *sh;
    cudaGetSymbolAddress((void**)&a_hi, d_a_hi);
    cudaGetSymbolAddress((void**)&a_lo, d_a_lo);
    cudaGetSymbolAddress((void**)&b_hi, d_b_hi);
    cudaGetSymbolAddress((void**)&b_lo, d_b_lo);
    cudaGetSymbolAddress((void**)&a2_hi, d_a2_hi);
    cudaGetSymbolAddress((void**)&a2_lo, d_a2_lo);
    cudaGetSymbolAddress((void**)&w2_hi, d_w2_hi);
    cudaGetSymbolAddress((void**)&w2_lo, d_w2_lo);
    cudaGetSymbolAddress((void**)&part, d_part);
    cudaGetSymbolAddress((void**)&h0, d_h0);
    cudaGetSymbolAddress((void**)&h1, d_h1);
    cudaGetSymbolAddress((void**)&h2, d_h2);
    cudaGetSymbolAddress((void**)&pstat, d_pstat);
    cudaGetSymbolAddress((void**)&sc, d_scale);
    cudaGetSymbolAddress((void**)&sh, d_shift);

    static int smem_set = 0;
    if (!smem_set) {
        cudaFuncSetAttribute(gemm0_bf3w, cudaFuncAttributeMaxDynamicSharedMemorySize, G0_SMEM);
        cudaFuncSetAttribute(gemm_bf3, cudaFuncAttributeMaxDynamicSharedMemorySize, SMEM_G);
        smem_set = 1;
    }

    // 1) front end -> A hi/lo (bf16); mw0 split
    fuse_front<<<BATCH, 256>>>(x, emb, sw1, sb1, sw2, sb2, Wb1, Wb2, a_hi, a_lo);
    {
        size_t n = (size_t)HID * K1;
        split_b<<<(unsigned)((n + 255) / 256), 256>>>(mw0, b_hi, b_lo);
    }

    // 2) GEMM0 full-N (split-K=16) + fused reduce/BN-partials
    {
        dim3 grid(BATCH / G0_BM, KSPLIT0);   // (64, 16) = 1024 CTAs
        gemm0_bf3w<<<grid, 256, G0_SMEM>>>(a_hi, a_lo, b_hi, b_lo, part);
        reduce_h0_stats<<<NB, 256>>>(part, mb0, h0, pstat);
        stats_fin<<<HID, 128>>>(pstat, g0, be0, sc + 0 * HID, sh + 0 * HID);
    }

    // 3) layer 1
    conv_split<<<BATCH * K2P / 256, 256>>>(h0, sc + 0 * HID, sh + 0 * HID, a2_hi, a2_lo);
    wsplit<<<HID * K2P / 256, 256>>>(mw1, w2_hi, w2_lo);
    {
        dim3 grid(HID / BN, BATCH / BM, 1);
        gemm_bf3<<<grid, 256, SMEM_G>>>(a2_hi, a2_lo, w2_hi, w2_lo, h1, mb1, K2P);
    }
    bn_pass1<<<NB, 256>>>(h1, pstat);
    stats_fin<<<HID, 128>>>(pstat, g1, be1, sc + 1 * HID, sh + 1 * HID);

    // 4) layer 2
    conv_split<<<BATCH * K2P / 256, 256>>>(h1, sc + 1 * HID, sh + 1 * HID, a2_hi, a2_lo);
    wsplit<<<HID * K2P / 256, 256>>>(mw2, w2_hi, w2_lo);
    {
        dim3 grid(HID / BN, BATCH / BM, 1);
        gemm_bf3<<<grid, 256, SMEM_G>>>(a2_hi, a2_lo, w2_hi, w2_lo, h2, mb2, K2P);
    }
    bn_pass1<<<NB, 256>>>(h2, pstat);
    stats_fin<<<HID, 128>>>(pstat, g2, be2, sc + 2 * HID, sh + 2 * HID);

    // 5) final dot
    final_dot<<<(BATCH * 32 + 255) / 256, 256>>>(h2, sc + 2 * HID, sh + 2 * HID,
                                                 mw3, mb3, out);
}

// round 8
// speedup vs baseline: 2.2160x; 1.1107x over previous
#include <cuda_runtime.h>
#include <cuda_bf16.h>
#include <math.h>
#include <stdint.h>

// ---------------- problem constants ----------------
#define BATCH 4096
#define NF    39
#define NE    16
#define NPAIR 741
#define K1    (2 * NPAIR * NE)    // 23712
#define HID   400
#define K2P   416                 // HID padded for small layers
#define EPS   1e-5f

// ---------------- bf16 3x GEMM tiling (3-stage, 2 CTAs/SM) ----------------
#define BM 128
#define BN 80
#define A_ROWB 80                 // smem row stride bytes (32 halves + pad)
#define OFF_A0  10240             // 128*80
#define OFF_B1  20480
#define STAGE   33280             // A hi/lo + B hi/lo per stage
#define NSTAGE  3
#define SMEM_G  (STAGE * NSTAGE)  // 99840  -> 2 CTAs/SM
#define KSPLIT0 9
#define NB      512               // stat partial blocks
#define SQOFF   (HID * NB)

// ---------------- scratch ----------------
__device__ __nv_bfloat16 d_a_hi[(size_t)BATCH * K1];
__device__ __nv_bfloat16 d_a_lo[(size_t)BATCH * K1];
__device__ __nv_bfloat16 d_b_hi[(size_t)HID * K1];
__device__ __nv_bfloat16 d_b_lo[(size_t)HID * K1];
__device__ float d_part[(size_t)KSPLIT0 * BATCH * HID];
__device__ __nv_bfloat16 d_a2_hi[(size_t)BATCH * K2P];
__device__ __nv_bfloat16 d_a2_lo[(size_t)BATCH * K2P];
__device__ __nv_bfloat16 d_w2_hi[(size_t)HID * K2P];
__device__ __nv_bfloat16 d_w2_lo[(size_t)HID * K2P];
__device__ float d_h0[BATCH * HID];
__device__ float d_h1[BATCH * HID];
__device__ float d_h2[BATCH * HID];
__device__ float d_pstat[2 * NB * HID];
__device__ float d_scale[3][HID];
__device__ float d_shift[3][HID];

// ---------------- helpers ----------------
__device__ __forceinline__ uint32_t smem_u32(const void* p) {
    uint32_t a;
    asm("{ .reg .u64 t; cvta.to.shared.u64 t, %1; cvt.u32.u64 %0, t; }" : "=r"(a) : "l"(p));
    return a;
}

#define CP_ASYNC16(dst, src) \
    asm volatile("cp.async.cg.shared.global [%0], [%1], 16;" :: "r"(dst), "l"(src))
#define CP_COMMIT() asm volatile("cp.async.commit_group;" ::: "memory")
#define CP_WAIT1()  asm volatile("cp.async.wait_group 1;" ::: "memory")
#define CP_WAIT0()  asm volatile("cp.async.wait_group 0;" ::: "memory")

#define LDSM4(r0, r1, r2, r3, a) \
    asm volatile("ldmatrix.sync.aligned.m8n8.x4.shared.b16 {%0,%1,%2,%3}, [%4];" \
        : "=r"(r0), "=r"(r1), "=r"(r2), "=r"(r3) : "r"(a))
#define LDSM2(r0, r1, a) \
    asm volatile("ldmatrix.sync.aligned.m8n8.x2.shared.b16 {%0,%1}, [%2];" \
        : "=r"(r0), "=r"(r1) : "r"(a))

__device__ __forceinline__ void mma_bf16(float* c, const uint32_t* a, const uint32_t* b) {
    asm volatile(
        "mma.sync.aligned.m16n8k16.row.col.f32.bf16.bf16.f32 "
        "{%0,%1,%2,%3}, {%4,%5,%6,%7}, {%8,%9}, {%0,%1,%2,%3};"
        : "+f"(c[0]), "+f"(c[1]), "+f"(c[2]), "+f"(c[3])
        : "r"(a[0]), "r"(a[1]), "r"(a[2]), "r"(a[3]), "r"(b[0]), "r"(b[1]));
}

// =====================================================================
// Kernel 1: gather + SENET + bilinear -> A_hi / A_lo (bf16 split)
// =====================================================================
__global__ __launch_bounds__(256) void fuse_front(
    const int* __restrict__ x,
    const float* __restrict__ emb,
    const float* __restrict__ w1, const float* __restrict__ b1,
    const float* __restrict__ w2, const float* __restrict__ b2,
    const float* __restrict__ Wb1, const float* __restrict__ Wb2,
    __nv_bfloat16* __restrict__ a_hi, __nv_bfloat16* __restrict__ a_lo)
{
    __shared__ float xe[NF][NE];
    __shared__ float xs[NF][NE];
    __shared__ float p1[NF][NE];
    __shared__ float p2[NF][NE];
    __shared__ float zf[NF], av[NF], af[NF];
    __shared__ unsigned char ii[NPAIR], jj[NPAIR];
    __shared__ int is64;

    const int b = blockIdx.x;
    const int tid = threadIdx.x;

    if (tid == 0) {
        int f64 = 1;
        for (int w = 1; w < 2 * NF; w += 2)
            if (x[w] != 0) { f64 = 0; break; }
        is64 = f64;
    }
    for (int k = tid; k < NPAIR; k += 256) {
        int i = 0, rem = k;
        while (rem >= NF - 1 - i) { rem -= NF - 1 - i; i++; }
        ii[k] = (unsigned char)i;
        jj[k] = (unsigned char)(i + 1 + rem);
    }
    __syncthreads();

    for (int idx = tid; idx < NF * NE; idx += 256) {
        int f = idx >> 4, e = idx & 15;
        int xv = is64 ? x[2 * (b * NF + f)] : x[b * NF + f];
        xe[f][e] = emb[(xv + 1000 * f) * NE + e];
    }
    __syncthreads();

    if (tid < NF) {
        float m = xe[tid][0];
        #pragma unroll
        for (int e = 1; e < NE; e++) m = fmaxf(m, xe[tid][e]);
        zf[tid] = m;
    }
    __syncthreads();
    if (tid < NF) {
        float s = b1[tid];
        for (int j = 0; j < NF; j++) s += zf[j] * w1[tid * NF + j];
        av[tid] = fmaxf(s, 0.0f);
    }
    __syncthreads();
    if (tid < NF) {
        float s = b2[tid];
        for (int j = 0; j < NF; j++) s += av[j] * w2[tid * NF + j];
        af[tid] = fmaxf(s, 0.0f);
    }
    __syncthreads();

    for (int idx = tid; idx < NF * NE; idx += 256) {
        int f = idx >> 4, d = idx & 15;
        float s1 = 0.0f, s2 = 0.0f;
        #pragma unroll
        for (int e = 0; e < NE; e++) {
            float v = xe[f][e];
            s1 += v * Wb1[d * NE + e];
            s2 += v * Wb2[d * NE + e];
        }
        p1[f][d] = s1;
        p2[f][d] = af[f] * s2;
        xs[f][d] = af[f] * xe[f][d];
    }
    __syncthreads();

    __nv_bfloat16* ohi = a_hi + (size_t)b * K1;
    __nv_bfloat16* olo = a_lo + (size_t)b * K1;
    for (int idx = tid; idx < NPAIR * NE; idx += 256) {
        int k = idx >> 4, e = idx & 15;
        int i = ii[k], j = jj[k];
        float v1 = p1[i][e] * xe[j][e];
        float v2 = p2[i][e] * xs[j][e];
        __nv_bfloat16 h1 = __float2bfloat16(v1);
        __nv_bfloat16 h2 = __float2bfloat16(v2);
        ohi[idx] = h1;
        olo[idx] = __float2bfloat16(v1 - __bfloat162float(h1));
        ohi[idx + NPAIR * NE] = h2;
        olo[idx + NPAIR * NE] = __float2bfloat16(v2 - __bfloat162float(h2));
    }
}

// =====================================================================
// Kernel 1b: split mw0 into bf16 hi/lo
// =====================================================================
__global__ __launch_bounds__(256) void split_b(
    const float* __restrict__ w, __nv_bfloat16* __restrict__ hi,
    __nv_bfloat16* __restrict__ lo)
{
    size_t i = (size_t)blockIdx.x * 256 + threadIdx.x;
    size_t n = (size_t)HID * K1;
    if (i < n) {
        float v = w[i];
        __nv_bfloat16 h = __float2bfloat16(v);
        hi[i] = h;
        lo[i] = __float2bfloat16(v - __bfloat162float(h));
    }
}

// =====================================================================
// gemm_bf3: bf16 3-product GEMM, CTA 128x80, BK=32, 3-stage, 2 CTAs/SM
//   z-indexed split-K writes partials (bias==nullptr) or direct out+bias
// =====================================================================
__global__ __launch_bounds__(256, 2) void gemm_bf3(
    const __nv_bfloat16* __restrict__ aH, const __nv_bfloat16* __restrict__ aL,
    const __nv_bfloat16* __restrict__ bH, const __nv_bfloat16* __restrict__ bL,
    float* __restrict__ out, const float* __restrict__ bias,
    int Kst, int ksplit)
{
    extern __shared__ char smem[];
    const uint32_t sb = smem_u32(smem);
    const int tid  = threadIdx.x;
    const int wid  = tid >> 5;
    const int lane = tid & 31;

    const int nbase = blockIdx.x * BN;
    const int mbase = blockIdx.y * BM;
    const int z     = blockIdx.z;

    const int tilesTot = Kst / 32;
    const int qt = tilesTot / ksplit, rt = tilesTot % ksplit;
    const int t0 = z * qt + (z < rt ? z : rt);
    const int T  = qt + (z < rt ? 1 : 0);

    const int wm = (wid & 3) * 32;
    const int wn = (wid >> 2) * 40;
    const int grp = lane >> 2;
    const int qd  = lane & 3;

    const uint32_t aoff = (uint32_t)((wm + (lane & 15)) * A_ROWB + ((lane >> 4) * 16));
    const int rowB = (lane & 7) + ((lane >> 4) << 3);
    const int kB   = ((lane >> 3) & 1) * 16;
    const uint32_t boff  = (uint32_t)(OFF_B1 + (wn + rowB) * A_ROWB + kB);
    const uint32_t boff2 = (uint32_t)(OFF_B1 + (wn + 32 + (lane & 7)) * A_ROWB + kB);

    float acc[2][5][4];
    #pragma unroll
    for (int im = 0; im < 2; im++)
        #pragma unroll
        for (int in = 0; in < 5; in++)
            #pragma unroll
            for (int r = 0; r < 4; r++) acc[im][in][r] = 0.0f;

    auto load_tile = [&](int s, int t) {
        const int k0 = t * 32;
        const uint32_t st = sb + s * STAGE;
        #pragma unroll
        for (int i = 0; i < 2; i++) {                   // A: 512 chunks
            int idx = tid + i * 256;
            int rr = idx >> 2, ch = idx & 3;
            uint32_t dst = st + rr * A_ROWB + ch * 16;
            size_t g = (size_t)(mbase + rr) * Kst + k0 + ch * 8;
            CP_ASYNC16(dst, aH + g);
            CP_ASYNC16(dst + OFF_A0, aL + g);
        }
        if (tid < 320) {                                // B rows 0..79, 4 chunks
            int rr = tid >> 2, ch = tid & 3;
            uint32_t dst = st + OFF_B1 + rr * A_ROWB + ch * 16;
            size_t g = (size_t)(nbase + rr) * Kst + k0 + ch * 8;
            CP_ASYNC16(dst, bH + g);
            CP_ASYNC16(dst + 6400, bL + g);
        }
        if (tid < 64) {
            int idx = tid + 256;
            int rr = idx >> 2, ch = idx & 3;
            uint32_t dst = st + OFF_B1 + rr * A_ROWB + ch * 16;
            size_t g = (size_t)(nbase + rr) * Kst + k0 + ch * 8;
            CP_ASYNC16(dst, bH + g);
            CP_ASYNC16(dst + 6400, bL + g);
        }
        CP_COMMIT();
    };

    // prologue: depth-2 prefetch over 3 buffers (T >= 13 at all call sites)
    load_tile(0, t0);
    load_tile(1, t0 + 1);

    for (int u = 0; u < T; ++u) {
        if (u < T - 1) { CP_WAIT1(); } else { CP_WAIT0(); }
        __syncthreads();

        if (u + 2 < T) load_tile((u + 2) % NSTAGE, t0 + u + 2);

        const uint32_t sA = sb + (u % NSTAGE) * STAGE;
        #pragma unroll
        for (int ks = 0; ks < 2; ks++) {
            const uint32_t ka = ks * 32;
            uint32_t ah[2][4], al[2][4], bh[5][2], bl[5][2];
            LDSM4(ah[0][0], ah[0][1], ah[0][2], ah[0][3], sA + aoff + ka);
            LDSM4(ah[1][0], ah[1][1], ah[1][2], ah[1][3], sA + aoff + 1280 + ka);
            LDSM4(al[0][0], al[0][1], al[0][2], al[0][3], sA + aoff + OFF_A0 + ka);
            LDSM4(al[1][0], al[1][1], al[1][2], al[1][3], sA + aoff + OFF_A0 + 1280 + ka);
            LDSM4(bh[0][0], bh[0][1], bh[1][0], bh[1][1], sA + boff + ka);
            LDSM4(bh[2][0], bh[2][1], bh[3][0], bh[3][1], sA + boff + 1280 + ka);
            LDSM2(bh[4][0], bh[4][1], sA + boff2 + ka);
            LDSM4(bl[0][0], bl[0][1], bl[1][0], bl[1][1], sA + boff + 6400 + ka);
            LDSM4(bl[2][0], bl[2][1], bl[3][0], bl[3][1], sA + boff + 6400 + 1280 + ka);
            LDSM2(bl[4][0], bl[4][1], sA + boff2 + 6400 + ka);

            #pragma unroll
            for (int im = 0; im < 2; im++)
                #pragma unroll
                for (int in = 0; in < 5; in++) {
                    mma_bf16(acc[im][in], ah[im], bh[in]);
                    mma_bf16(acc[im][in], ah[im], bl[in]);
                    mma_bf16(acc[im][in], al[im], bh[in]);
                }
        }
    }

    const size_t outBase = (size_t)z * BATCH * HID;
    #pragma unroll
    for (int im = 0; im < 2; im++) {
        #pragma unroll
        for (int in = 0; in < 5; in++) {
            int row = mbase + wm + im * 16 + grp;
            int col = nbase + wn + in * 8 + qd * 2;
            float b0v = 0.f, b1v = 0.f;
            if (bias) { b0v = bias[col]; b1v = bias[col + 1]; }
            float* d = out + outBase + (size_t)row * HID + col;
            *(float2*)d = make_float2(acc[im][in][0] + b0v, acc[im][in][1] + b1v);
            *(float2*)(d + 8 * HID) = make_float2(acc[im][in][2] + b0v, acc[im][in][3] + b1v);
        }
    }
}

// =====================================================================
// reduce split-K partials + bias -> h0, fused BN partials
// =====================================================================
__global__ __launch_bounds__(256) void reduce_h0_stats(
    const float* __restrict__ part, const float* __restrict__ bias,
    float* __restrict__ h0, float* __restrict__ pstat)
{
    const int blk = blockIdx.x;
    const int t = threadIdx.x;
    const int r0 = blk * (BATCH / NB);
    const int c0 = t, c1 = t + 256;
    const float bi0 = bias[c0];
    float bi1 = 0.f;
    if (c1 < HID) bi1 = bias[c1];

    float s0 = 0.f, q0 = 0.f, s1 = 0.f, q1 = 0.f;
    for (int r = 0; r < BATCH / NB; r++) {
        size_t base = (size_t)(r0 + r) * HID;
        {
            float v = bi0;
            #pragma unroll
            for (int zz = 0; zz < KSPLIT0; zz++)
                v += part[(size_t)zz * BATCH * HID + base + c0];
            h0[base + c0] = v; s0 += v; q0 += v * v;
        }
        if (c1 < HID) {
            float v = bi1;
            #pragma unroll
            for (int zz = 0; zz < KSPLIT0; zz++)
                v += part[(size_t)zz * BATCH * HID + base + c1];
            h0[base + c1] = v; s1 += v; q1 += v * v;
        }
    }
    pstat[c0 * NB + blk] = s0; pstat[SQOFF + c0 * NB + blk] = q0;
    if (c1 < HID) { pstat[c1 * NB + blk] = s1; pstat[SQOFF + c1 * NB + blk] = q1; }
}

// =====================================================================
// BN pass1 / finalize
// =====================================================================
__global__ __launch_bounds__(256) void bn_pass1(
    const float* __restrict__ h, float* __restrict__ pstat)
{
    const int blk = blockIdx.x;
    const int t = threadIdx.x;
    const int r0 = blk * (BATCH / NB);
    const int c0 = t, c1 = t + 256;
    float s0 = 0.f, q0 = 0.f, s1 = 0.f, q1 = 0.f;
    for (int r = 0; r < BATCH / NB; r++) {
        size_t base = (size_t)(r0 + r) * HID;
        float v = h[base + c0]; s0 += v; q0 += v * v;
        if (c1 < HID) { float w = h[base + c1]; s1 += w; q1 += w * w; }
    }
    pstat[c0 * NB + blk] = s0; pstat[SQOFF + c0 * NB + blk] = q0;
    if (c1 < HID) { pstat[c1 * NB + blk] = s1; pstat[SQOFF + c1 * NB + blk] = q1; }
}

__global__ __launch_bounds__(128) void stats_fin(
    const float* __restrict__ pstat, const float* __restrict__ g,
    const float* __restrict__ be, float* __restrict__ sc, float* __restrict__ sh)
{
    __shared__ float ss[128], sq[128];
    const int c = blockIdx.x, t = threadIdx.x;
    float s = 0.f, q = 0.f;
    for (int i = t; i < NB; i += 128) {
        s += pstat[c * NB + i];
        q += pstat[SQOFF + c * NB + i];
    }
    ss[t] = s; sq[t] = q;
    __syncthreads();
    for (int o = 64; o > 0; o >>= 1) {
        if (t < o) { ss[t] += ss[t + o]; sq[t] += sq[t + o]; }
        __syncthreads();
    }
    if (t == 0) {
        double mu = (double)ss[0] / BATCH;
        double var = (double)sq[0] / BATCH - mu * mu;
        if (var < 0.0) var = 0.0;
        float rstd = (float)(1.0 / sqrt(var + (double)EPS));
        float scv = g[c] * rstd;
        sc[c] = scv;
        sh[c] = be[c] - (float)mu * scv;
    }
}

// =====================================================================
// conv_split / wsplit
// =====================================================================
__global__ __launch_bounds__(256) void conv_split(
    const float* __restrict__ h, const float* __restrict__ sc,
    const float* __restrict__ sh,
    __nv_bfloat16* __restrict__ hi, __nv_bfloat16* __restrict__ lo)
{
    int idx = blockIdx.x * 256 + threadIdx.x;
    int row = idx / K2P, col = idx - row * K2P;
    float v = 0.0f;
    if (col < HID)
        v = fmaxf(h[(size_t)row * HID + col] * sc[col] + sh[col], 0.0f);
    __nv_bfloat16 hh = __float2bfloat16(v);
    hi[idx] = hh;
    lo[idx] = __float2bfloat16(v - __bfloat162float(hh));
}

__global__ __launch_bounds__(256) void wsplit(
    const float* __restrict__ w, __nv_bfloat16* __restrict__ hi,
    __nv_bfloat16* __restrict__ lo)
{
    int idx = blockIdx.x * 256 + threadIdx.x;
    int row = idx / K2P, col = idx - row * K2P;
    float v = (col < HID) ? w[row * HID + col] : 0.0f;
    __nv_bfloat16 h = __float2bfloat16(v);
    hi[idx] = h;
    lo[idx] = __float2bfloat16(v - __bfloat162float(h));
}

// =====================================================================
// final dot
// =====================================================================
__global__ __launch_bounds__(256) void final_dot(
    const float* __restrict__ h, const float* __restrict__ scale,
    const float* __restrict__ shift, const float* __restrict__ w3,
    const float* __restrict__ b3, float* __restrict__ out)
{
    const int gtid = blockIdx.x * blockDim.x + threadIdx.x;
    const int warp = gtid >> 5;
    const int lane = gtid & 31;
    if (warp >= BATCH) return;
    float s = 0.0f;
    for (int k = lane; k < HID; k += 32) {
        float v = fmaxf(h[(size_t)warp * HID + k] * scale[k] + shift[k], 0.0f);
        s += v * w3[k];
    }
    #pragma unroll
    for (int off = 16; off > 0; off >>= 1)
        s += __shfl_down_sync(0xFFFFFFFFu, s, off);
    if (lane == 0) out[warp] = s + b3[0];
}

// =====================================================================
// launcher
// =====================================================================
extern "C" void kernel_launch(void* const* d_in, const int* in_sizes, int n_in,
                              void* d_out, int out_size)
{
    const int*   x    = (const int*)  d_in[0];
    const float* emb  = (const float*)d_in[1];
    const float* sw1  = (const float*)d_in[2];
    const float* sb1  = (const float*)d_in[3];
    const float* sw2  = (const float*)d_in[4];
    const float* sb2  = (const float*)d_in[5];
    const float* Wb1  = (const float*)d_in[6];
    const float* Wb2  = (const float*)d_in[7];
    const float* mw0  = (const float*)d_in[8];
    const float* mb0  = (const float*)d_in[9];
    const float* g0   = (const float*)d_in[10];
    const float* be0  = (const float*)d_in[11];
    const float* mw1  = (const float*)d_in[12];
    const float* mb1  = (const float*)d_in[13];
    const float* g1   = (const float*)d_in[14];
    const float* be1  = (const float*)d_in[15];
    const float* mw2  = (const float*)d_in[16];
    const float* mb2  = (const float*)d_in[17];
    const float* g2   = (const float*)d_in[18];
    const float* be2  = (const float*)d_in[19];
    const float* mw3  = (const float*)d_in[20];
    const float* mb3  = (const float*)d_in[21];
    float* out = (float*)d_out;

    __nv_bfloat16 *a_hi, *a_lo, *b_hi, *b_lo, *a2_hi, *a2_lo, *w2_hi, *w2_lo;
    float *part, *h0, *h1, *h2, *pstat, *sc, *sh;
    cudaGetSymbolAddress((void**)&a_hi, d_a_hi);
    cudaGetSymbolAddress((void**)&a_lo, d_a_lo);
    cudaGetSymbolAddress((void**)&b_hi, d_b_hi);
    cudaGetSymbolAddress((void**)&b_lo, d_b_lo);
    cudaGetSymbolAddress((void**)&a2_hi, d_a2_hi);
    cudaGetSymbolAddress((void**)&a2_lo, d_a2_lo);
    cudaGetSymbolAddress((void**)&w2_hi, d_w2_hi);
    cudaGetSymbolAddress((void**)&w2_lo, d_w2_lo);
    cudaGetSymbolAddress((void**)&part, d_part);
    cudaGetSymbolAddress((void**)&h0, d_h0);
    cudaGetSymbolAddress((void**)&h1, d_h1);
    cudaGetSymbolAddress((void**)&h2, d_h2);
    cudaGetSymbolAddress((void**)&pstat, d_pstat);
    cudaGetSymbolAddress((void**)&sc, d_scale);
    cudaGetSymbolAddress((void**)&sh, d_shift);

    static int smem_set = 0;
    if (!smem_set) {
        cudaFuncSetAttribute(gemm_bf3, cudaFuncAttributeMaxDynamicSharedMemorySize, SMEM_G);
        smem_set = 1;
    }

    // 1) front end -> A hi/lo (bf16); mw0 split
    fuse_front<<<BATCH, 256>>>(x, emb, sw1, sb1, sw2, sb2, Wb1, Wb2, a_hi, a_lo);
    {
        size_t n = (size_t)HID * K1;
        split_b<<<(unsigned)((n + 255) / 256), 256>>>(mw0, b_hi, b_lo);
    }

    // 2) GEMM0 (split-K=9, 2 CTAs/SM) + fused reduce/BN-partials
    {
        dim3 grid(HID / BN, BATCH / BM, KSPLIT0);   // (5, 32, 9) = 1440 CTAs
        gemm_bf3<<<grid, 256, SMEM_G>>>(a_hi, a_lo, b_hi, b_lo, part, nullptr,
                                        K1, KSPLIT0);
        reduce_h0_stats<<<NB, 256>>>(part, mb0, h0, pstat);
        stats_fin<<<HID, 128>>>(pstat, g0, be0, sc + 0 * HID, sh + 0 * HID);
    }

    // 3) layer 1
    conv_split<<<BATCH * K2P / 256, 256>>>(h0, sc + 0 * HID, sh + 0 * HID, a2_hi, a2_lo);
    wsplit<<<HID * K2P / 256, 256>>>(mw1, w2_hi, w2_lo);
    {
        dim3 grid(HID / BN, BATCH / BM, 1);
        gemm_bf3<<<grid, 256, SMEM_G>>>(a2_hi, a2_lo, w2_hi, w2_lo, h1, mb1, K2P, 1);
    }
    bn_pass1<<<NB, 256>>>(h1, pstat);
    stats_fin<<<HID, 128>>>(pstat, g1, be1, sc + 1 * HID, sh + 1 * HID);

    // 4) layer 2
    conv_split<<<BATCH * K2P / 256, 256>>>(h1, sc + 1 * HID, sh + 1 * HID, a2_hi, a2_lo);
    wsplit<<<HID * K2P / 256, 256>>>(mw2, w2_hi, w2_lo);
    {
        dim3 grid(HID / BN, BATCH / BM, 1);
        gemm_bf3<<<grid, 256, SMEM_G>>>(a2_hi, a2_lo, w2_hi, w2_lo, h2, mb2, K2P, 1);
    }
    bn_pass1<<<NB, 256>>>(h2, pstat);
    stats_fin<<<HID, 128>>>(pstat, g2, be2, sc + 2 * HID, sh + 2 * HID);

    // 5) final dot
    final_dot<<<(BATCH * 32 + 255) / 256, 256>>>(h2, sc + 2 * HID, sh + 2 * HID,
                                                 mw3, mb3, out);
}

// round 9
// speedup vs baseline: 3.2176x; 1.4520x over previous
#include <cuda_runtime.h>
#include <cuda_fp16.h>
#include <math.h>
#include <stdint.h>

// ---------------- problem constants ----------------
#define BATCH 4096
#define NF    39
#define NE    16
#define NPAIR 741
#define K1    (2 * NPAIR * NE)    // 23712
#define HID   400
#define K2P   416                 // HID padded for small layers
#define EPS   1e-5f

// quantization scales
#define SA0   8192.0f             // A scale for gemm0 (2^13)
#define SB0   4096.0f             // B scale (2^12)
#define INVS0 (1.0f / (SA0 * SB0))
#define SB2   4096.0f             // weight scale small layers
#define INVS2 (1.0f / SB2)

// ---------------- fp16 2-product GEMM tiling (4-stage, 2 CTAs/SM) ----------------
#define BM 128
#define BN 80
#define A_ROWB 80                 // smem row stride bytes (32 halves + pad)
#define OFF_BH  10240             // A: 128*80
#define OFF_BL  16640             // +80*80
#define STAGE   23040
#define NSTAGE  4
#define SMEM_G  (STAGE * NSTAGE)  // 92160 -> 2 CTAs/SM
#define KSPLIT0 9
#define NB      512               // stat partial blocks
#define SQOFF   (HID * NB)

// ---------------- scratch ----------------
__device__ __half d_a[(size_t)BATCH * K1];        // 194 MB
__device__ __half d_bh[(size_t)HID * K1];
__device__ __half d_bl[(size_t)HID * K1];
__device__ float d_part[(size_t)KSPLIT0 * BATCH * HID];
__device__ __half d_a2[(size_t)BATCH * K2P];
__device__ __half d_w2h[(size_t)HID * K2P];
__device__ __half d_w2l[(size_t)HID * K2P];
__device__ float d_h0[BATCH * HID];
__device__ float d_h1[BATCH * HID];
__device__ float d_h2[BATCH * HID];
__device__ float d_pstat[2 * NB * HID];
__device__ float d_scale[3][HID];
__device__ float d_shift[3][HID];

// ---------------- helpers ----------------
__device__ __forceinline__ uint32_t smem_u32(const void* p) {
    uint32_t a;
    asm("{ .reg .u64 t; cvta.to.shared.u64 t, %1; cvt.u32.u64 %0, t; }" : "=r"(a) : "l"(p));
    return a;
}

#define CP_ASYNC16(dst, src) \
    asm volatile("cp.async.cg.shared.global [%0], [%1], 16;" :: "r"(dst), "l"(src))
#define CP_COMMIT() asm volatile("cp.async.commit_group;" ::: "memory")
#define CP_WAIT2()  asm volatile("cp.async.wait_group 2;" ::: "memory")
#define CP_WAIT1()  asm volatile("cp.async.wait_group 1;" ::: "memory")
#define CP_WAIT0()  asm volatile("cp.async.wait_group 0;" ::: "memory")

#define LDSM4(r0, r1, r2, r3, a) \
    asm volatile("ldmatrix.sync.aligned.m8n8.x4.shared.b16 {%0,%1,%2,%3}, [%4];" \
        : "=r"(r0), "=r"(r1), "=r"(r2), "=r"(r3) : "r"(a))
#define LDSM2(r0, r1, a) \
    asm volatile("ldmatrix.sync.aligned.m8n8.x2.shared.b16 {%0,%1}, [%2];" \
        : "=r"(r0), "=r"(r1) : "r"(a))

__device__ __forceinline__ void mma_f16(float* c, const uint32_t* a, const uint32_t* b) {
    asm volatile(
        "mma.sync.aligned.m16n8k16.row.col.f32.f16.f16.f32 "
        "{%0,%1,%2,%3}, {%4,%5,%6,%7}, {%8,%9}, {%0,%1,%2,%3};"
        : "+f"(c[0]), "+f"(c[1]), "+f"(c[2]), "+f"(c[3])
        : "r"(a[0]), "r"(a[1]), "r"(a[2]), "r"(a[3]), "r"(b[0]), "r"(b[1]));
}

// =====================================================================
// Kernel 1: gather + SENET + bilinear -> A (scaled fp16)
// =====================================================================
__global__ __launch_bounds__(256) void fuse_front(
    const int* __restrict__ x,
    const float* __restrict__ emb,
    const float* __restrict__ w1, const float* __restrict__ b1,
    const float* __restrict__ w2, const float* __restrict__ b2,
    const float* __restrict__ Wb1, const float* __restrict__ Wb2,
    __half* __restrict__ a_out)
{
    __shared__ float xe[NF][NE];
    __shared__ float xs[NF][NE];
    __shared__ float p1[NF][NE];
    __shared__ float p2[NF][NE];
    __shared__ float zf[NF], av[NF], af[NF];
    __shared__ unsigned char ii[NPAIR], jj[NPAIR];
    __shared__ int is64;

    const int b = blockIdx.x;
    const int tid = threadIdx.x;

    if (tid == 0) {
        int f64 = 1;
        for (int w = 1; w < 2 * NF; w += 2)
            if (x[w] != 0) { f64 = 0; break; }
        is64 = f64;
    }
    for (int k = tid; k < NPAIR; k += 256) {
        int i = 0, rem = k;
        while (rem >= NF - 1 - i) { rem -= NF - 1 - i; i++; }
        ii[k] = (unsigned char)i;
        jj[k] = (unsigned char)(i + 1 + rem);
    }
    __syncthreads();

    for (int idx = tid; idx < NF * NE; idx += 256) {
        int f = idx >> 4, e = idx & 15;
        int xv = is64 ? x[2 * (b * NF + f)] : x[b * NF + f];
        xe[f][e] = emb[(xv + 1000 * f) * NE + e];
    }
    __syncthreads();

    if (tid < NF) {
        float m = xe[tid][0];
        #pragma unroll
        for (int e = 1; e < NE; e++) m = fmaxf(m, xe[tid][e]);
        zf[tid] = m;
    }
    __syncthreads();
    if (tid < NF) {
        float s = b1[tid];
        for (int j = 0; j < NF; j++) s += zf[j] * w1[tid * NF + j];
        av[tid] = fmaxf(s, 0.0f);
    }
    __syncthreads();
    if (tid < NF) {
        float s = b2[tid];
        for (int j = 0; j < NF; j++) s += av[j] * w2[tid * NF + j];
        af[tid] = fmaxf(s, 0.0f);
    }
    __syncthreads();

    for (int idx = tid; idx < NF * NE; idx += 256) {
        int f = idx >> 4, d = idx & 15;
        float s1 = 0.0f, s2 = 0.0f;
        #pragma unroll
        for (int e = 0; e < NE; e++) {
            float v = xe[f][e];
            s1 += v * Wb1[d * NE + e];
            s2 += v * Wb2[d * NE + e];
        }
        p1[f][d] = s1;
        p2[f][d] = af[f] * s2;
        xs[f][d] = af[f] * xe[f][d];
    }
    __syncthreads();

    __half* oa = a_out + (size_t)b * K1;
    for (int idx = tid; idx < NPAIR * NE; idx += 256) {
        int k = idx >> 4, e = idx & 15;
        int i = ii[k], j = jj[k];
        float v1 = p1[i][e] * xe[j][e];
        float v2 = p2[i][e] * xs[j][e];
        oa[idx]              = __float2half(v1 * SA0);
        oa[idx + NPAIR * NE] = __float2half(v2 * SA0);
    }
}

// =====================================================================
// Kernel 1b: split mw0 rows into scaled fp16 hi/lo
// =====================================================================
__global__ __launch_bounds__(256) void split_b(
    const float* __restrict__ w, __half* __restrict__ bh,
    __half* __restrict__ bl)
{
    size_t i = (size_t)blockIdx.x * 256 + threadIdx.x;
    size_t n = (size_t)HID * K1;
    if (i < n) {
        float t = w[i] * SB0;
        __half h = __float2half(t);
        bh[i] = h;
        bl[i] = __float2half(t - __half2float(h));
    }
}

// =====================================================================
// gemm_f16: 2-product fp16 GEMM, CTA 128x80, BK=32, 4-stage, 2 CTAs/SM
//   out[z][m,n] = invs * sum_k A[m,k]*(Bh+Bl)[n,k]  (+bias if non-null)
// =====================================================================
__global__ __launch_bounds__(256, 2) void gemm_f16(
    const __half* __restrict__ A,
    const __half* __restrict__ Bh, const __half* __restrict__ Bl,
    float* __restrict__ out, const float* __restrict__ bias,
    float invs, int Kst, int ksplit)
{
    extern __shared__ char smem[];
    const uint32_t sb = smem_u32(smem);
    const int tid  = threadIdx.x;
    const int wid  = tid >> 5;
    const int lane = tid & 31;

    const int nbase = blockIdx.x * BN;
    const int mbase = blockIdx.y * BM;
    const int z     = blockIdx.z;

    const int tilesTot = Kst / 32;
    const int qt = tilesTot / ksplit, rt = tilesTot % ksplit;
    const int t0 = z * qt + (z < rt ? z : rt);
    const int T  = qt + (z < rt ? 1 : 0);

    const int wm = (wid & 3) * 32;
    const int wn = (wid >> 2) * 40;
    const int grp = lane >> 2;
    const int qd  = lane & 3;

    const uint32_t aoff = (uint32_t)((wm + (lane & 15)) * A_ROWB + ((lane >> 4) * 16));
    const int rowB = (lane & 7) + ((lane >> 4) << 3);
    const int kB   = ((lane >> 3) & 1) * 16;
    const uint32_t boff  = (uint32_t)(OFF_BH + (wn + rowB) * A_ROWB + kB);
    const uint32_t boff2 = (uint32_t)(OFF_BH + (wn + 32 + (lane & 7)) * A_ROWB + kB);

    float acc[2][5][4];
    #pragma unroll
    for (int im = 0; im < 2; im++)
        #pragma unroll
        for (int in = 0; in < 5; in++)
            #pragma unroll
            for (int r = 0; r < 4; r++) acc[im][in][r] = 0.0f;

    auto load_tile = [&](int s, int t) {
        const int k0 = t * 32;
        const uint32_t st = sb + s * STAGE;
        #pragma unroll
        for (int i = 0; i < 2; i++) {                   // A: 512 chunks
            int idx = tid + i * 256;
            int rr = idx >> 2, ch = idx & 3;
            uint32_t dst = st + rr * A_ROWB + ch * 16;
            size_t g = (size_t)(mbase + rr) * Kst + k0 + ch * 8;
            CP_ASYNC16(dst, A + g);
        }
        {                                               // B rows 0..63
            int rr = tid >> 2, ch = tid & 3;
            uint32_t dst = st + OFF_BH + rr * A_ROWB + ch * 16;
            size_t g = (size_t)(nbase + rr) * Kst + k0 + ch * 8;
            CP_ASYNC16(dst, Bh + g);
            CP_ASYNC16(dst + (OFF_BL - OFF_BH), Bl + g);
        }
        if (tid < 64) {                                 // B rows 64..79
            int idx = tid + 256;
            int rr = idx >> 2, ch = idx & 3;
            uint32_t dst = st + OFF_BH + rr * A_ROWB + ch * 16;
            size_t g = (size_t)(nbase + rr) * Kst + k0 + ch * 8;
            CP_ASYNC16(dst, Bh + g);
            CP_ASYNC16(dst + (OFF_BL - OFF_BH), Bl + g);
        }
        CP_COMMIT();
    };

    // prologue: 3 tiles in flight over 4 buffers (T >= 13 at all call sites)
    load_tile(0, t0);
    load_tile(1, t0 + 1);
    load_tile(2, t0 + 2);

    for (int u = 0; u < T; ++u) {
        const int rem = T - 1 - u;
        if (rem >= 2) { CP_WAIT2(); } else if (rem == 1) { CP_WAIT1(); } else { CP_WAIT0(); }
        __syncthreads();

        if (u + 3 < T) load_tile((u + 3) & 3, t0 + u + 3);

        const uint32_t sA = sb + (u & 3) * STAGE;
        #pragma unroll
        for (int ks = 0; ks < 2; ks++) {
            const uint32_t ka = ks * 32;
            uint32_t a[2][4], bh[5][2], bl[5][2];
            LDSM4(a[0][0], a[0][1], a[0][2], a[0][3], sA + aoff + ka);
            LDSM4(a[1][0], a[1][1], a[1][2], a[1][3], sA + aoff + 1280 + ka);
            LDSM4(bh[0][0], bh[0][1], bh[1][0], bh[1][1], sA + boff + ka);
            LDSM4(bh[2][0], bh[2][1], bh[3][0], bh[3][1], sA + boff + 1280 + ka);
            LDSM2(bh[4][0], bh[4][1], sA + boff2 + ka);
            LDSM4(bl[0][0], bl[0][1], bl[1][0], bl[1][1], sA + boff + (OFF_BL - OFF_BH) + ka);
            LDSM4(bl[2][0], bl[2][1], bl[3][0], bl[3][1], sA + boff + (OFF_BL - OFF_BH) + 1280 + ka);
            LDSM2(bl[4][0], bl[4][1], sA + boff2 + (OFF_BL - OFF_BH) + ka);

            #pragma unroll
            for (int im = 0; im < 2; im++)
                #pragma unroll
                for (int in = 0; in < 5; in++) {
                    mma_f16(acc[im][in], a[im], bh[in]);
                    mma_f16(acc[im][in], a[im], bl[in]);
                }
        }
    }

    const size_t outBase = (size_t)z * BATCH * HID;
    #pragma unroll
    for (int im = 0; im < 2; im++) {
        #pragma unroll
        for (int in = 0; in < 5; in++) {
            int row = mbase + wm + im * 16 + grp;
            int col = nbase + wn + in * 8 + qd * 2;
            float b0v = 0.f, b1v = 0.f;
            if (bias) { b0v = bias[col]; b1v = bias[col + 1]; }
            float* d = out + outBase + (size_t)row * HID + col;
            *(float2*)d = make_float2(acc[im][in][0] * invs + b0v,
                                      acc[im][in][1] * invs + b1v);
            *(float2*)(d + 8 * HID) = make_float2(acc[im][in][2] * invs + b0v,
                                                  acc[im][in][3] * invs + b1v);
        }
    }
}

// =====================================================================
// reduce split-K partials + bias -> h0, fused BN partials
// =====================================================================
__global__ __launch_bounds__(256) void reduce_h0_stats(
    const float* __restrict__ part, const float* __restrict__ bias,
    float* __restrict__ h0, float* __restrict__ pstat)
{
    const int blk = blockIdx.x;
    const int t = threadIdx.x;
    const int r0 = blk * (BATCH / NB);
    const int c0 = t, c1 = t + 256;
    const float bi0 = bias[c0];
    float bi1 = 0.f;
    if (c1 < HID) bi1 = bias[c1];

    float s0 = 0.f, q0 = 0.f, s1 = 0.f, q1 = 0.f;
    for (int r = 0; r < BATCH / NB; r++) {
        size_t base = (size_t)(r0 + r) * HID;
        {
            float v = bi0;
            #pragma unroll
            for (int zz = 0; zz < KSPLIT0; zz++)
                v += part[(size_t)zz * BATCH * HID + base + c0];
            h0[base + c0] = v; s0 += v; q0 += v * v;
        }
        if (c1 < HID) {
            float v = bi1;
            #pragma unroll
            for (int zz = 0; zz < KSPLIT0; zz++)
                v += part[(size_t)zz * BATCH * HID + base + c1];
            h0[base + c1] = v; s1 += v; q1 += v * v;
        }
    }
    pstat[c0 * NB + blk] = s0; pstat[SQOFF + c0 * NB + blk] = q0;
    if (c1 < HID) { pstat[c1 * NB + blk] = s1; pstat[SQOFF + c1 * NB + blk] = q1; }
}

// =====================================================================
// BN pass1 / finalize
// =====================================================================
__global__ __launch_bounds__(256) void bn_pass1(
    const float* __restrict__ h, float* __restrict__ pstat)
{
    const int blk = blockIdx.x;
    const int t = threadIdx.x;
    const int r0 = blk * (BATCH / NB);
    const int c0 = t, c1 = t + 256;
    float s0 = 0.f, q0 = 0.f, s1 = 0.f, q1 = 0.f;
    for (int r = 0; r < BATCH / NB; r++) {
        size_t base = (size_t)(r0 + r) * HID;
        float v = h[base + c0]; s0 += v; q0 += v * v;
        if (c1 < HID) { float w = h[base + c1]; s1 += w; q1 += w * w; }
    }
    pstat[c0 * NB + blk] = s0; pstat[SQOFF + c0 * NB + blk] = q0;
    if (c1 < HID) { pstat[c1 * NB + blk] = s1; pstat[SQOFF + c1 * NB + blk] = q1; }
}

__global__ __launch_bounds__(128) void stats_fin(
    const float* __restrict__ pstat, const float* __restrict__ g,
    const float* __restrict__ be, float* __restrict__ sc, float* __restrict__ sh)
{
    __shared__ float ss[128], sq[128];
    const int c = blockIdx.x, t = threadIdx.x;
    float s = 0.f, q = 0.f;
    for (int i = t; i < NB; i += 128) {
        s += pstat[c * NB + i];
        q += pstat[SQOFF + c * NB + i];
    }
    ss[t] = s; sq[t] = q;
    __syncthreads();
    for (int o = 64; o > 0; o >>= 1) {
        if (t < o) { ss[t] += ss[t + o]; sq[t] += sq[t + o]; }
        __syncthreads();
    }
    if (t == 0) {
        double mu = (double)ss[0] / BATCH;
        double var = (double)sq[0] / BATCH - mu * mu;
        if (var < 0.0) var = 0.0;
        float rstd = (float)(1.0 / sqrt(var + (double)EPS));
        float scv = g[c] * rstd;
        sc[c] = scv;
        sh[c] = be[c] - (float)mu * scv;
    }
}

// =====================================================================
// conv_split: relu(bn(h)) -> fp16 [BATCH][K2P] (unscaled)
// wsplit: weight -> scaled fp16 hi/lo [HID][K2P]
// =====================================================================
__global__ __launch_bounds__(256) void conv_split(
    const float* __restrict__ h, const float* __restrict__ sc,
    const float* __restrict__ sh, __half* __restrict__ a2)
{
    int idx = blockIdx.x * 256 + threadIdx.x;
    int row = idx / K2P, col = idx - row * K2P;
    float v = 0.0f;
    if (col < HID)
        v = fmaxf(h[(size_t)row * HID + col] * sc[col] + sh[col], 0.0f);
    a2[idx] = __float2half(v);
}

__global__ __launch_bounds__(256) void wsplit(
    const float* __restrict__ w, __half* __restrict__ wh,
    __half* __restrict__ wl)
{
    int idx = blockIdx.x * 256 + threadIdx.x;
    int row = idx / K2P, col = idx - row * K2P;
    float v = (col < HID) ? w[row * HID + col] * SB2 : 0.0f;
    __half h = __float2half(v);
    wh[idx] = h;
    wl[idx] = __float2half(v - __half2float(h));
}

// =====================================================================
// final dot
// =====================================================================
__global__ __launch_bounds__(256) void final_dot(
    const float* __restrict__ h, const float* __restrict__ scale,
    const float* __restrict__ shift, const float* __restrict__ w3,
    const float* __restrict__ b3, float* __restrict__ out)
{
    const int gtid = blockIdx.x * blockDim.x + threadIdx.x;
    const int warp = gtid >> 5;
    const int lane = gtid & 31;
    if (warp >= BATCH) return;
    float s = 0.0f;
    for (int k = lane; k < HID; k += 32) {
        float v = fmaxf(h[(size_t)warp * HID + k] * scale[k] + shift[k], 0.0f);
        s += v * w3[k];
    }
    #pragma unroll
    for (int off = 16; off > 0; off >>= 1)
        s += __shfl_down_sync(0xFFFFFFFFu, s, off);
    if (lane == 0) out[warp] = s + b3[0];
}

// =====================================================================
// launcher
// =====================================================================
extern "C" void kernel_launch(void* const* d_in, const int* in_sizes, int n_in,
                              void* d_out, int out_size)
{
    const int*   x    = (const int*)  d_in[0];
    const float* emb  = (const float*)d_in[1];
    const float* sw1  = (const float*)d_in[2];
    const float* sb1  = (const float*)d_in[3];
    const float* sw2  = (const float*)d_in[4];
    const float* sb2  = (const float*)d_in[5];
    const float* Wb1  = (const float*)d_in[6];
    const float* Wb2  = (const float*)d_in[7];
    const float* mw0  = (const float*)d_in[8];
    const float* mb0  = (const float*)d_in[9];
    const float* g0   = (const float*)d_in[10];
    const float* be0  = (const float*)d_in[11];
    const float* mw1  = (const float*)d_in[12];
    const float* mb1  = (const float*)d_in[13];
    const float* g1   = (const float*)d_in[14];
    const float* be1  = (const float*)d_in[15];
    const float* mw2  = (const float*)d_in[16];
    const float* mb2  = (const float*)d_in[17];
    const float* g2   = (const float*)d_in[18];
    const float* be2  = (const float*)d_in[19];
    const float* mw3  = (const float*)d_in[20];
    const float* mb3  = (const float*)d_in[21];
    float* out = (float*)d_out;

    __half *a, *bh, *bl, *a2, *w2h, *w2l;
    float *part, *h0, *h1, *h2, *pstat, *sc, *sh;
    cudaGetSymbolAddress((void**)&a,  d_a);
    cudaGetSymbolAddress((void**)&bh, d_bh);
    cudaGetSymbolAddress((void**)&bl, d_bl);
    cudaGetSymbolAddress((void**)&a2, d_a2);
    cudaGetSymbolAddress((void**)&w2h, d_w2h);
    cudaGetSymbolAddress((void**)&w2l, d_w2l);
    cudaGetSymbolAddress((void**)&part, d_part);
    cudaGetSymbolAddress((void**)&h0, d_h0);
    cudaGetSymbolAddress((void**)&h1, d_h1);
    cudaGetSymbolAddress((void**)&h2, d_h2);
    cudaGetSymbolAddress((void**)&pstat, d_pstat);
    cudaGetSymbolAddress((void**)&sc, d_scale);
    cudaGetSymbolAddress((void**)&sh, d_shift);

    static int smem_set = 0;
    if (!smem_set) {
        cudaFuncSetAttribute(gemm_f16, cudaFuncAttributeMaxDynamicSharedMemorySize, SMEM_G);
        smem_set = 1;
    }

    // 1) front end -> A (scaled fp16); mw0 split (scaled fp16 hi/lo)
    fuse_front<<<BATCH, 256>>>(x, emb, sw1, sb1, sw2, sb2, Wb1, Wb2, a);
    {
        size_t n = (size_t)HID * K1;
        split_b<<<(unsigned)((n + 255) / 256), 256>>>(mw0, bh, bl);
    }

    // 2) GEMM0 (split-K=9, 2 CTAs/SM) + fused reduce/BN-partials
    {
        dim3 grid(HID / BN, BATCH / BM, KSPLIT0);   // (5, 32, 9) = 1440 CTAs
        gemm_f16<<<grid, 256, SMEM_G>>>(a, bh, bl, part, nullptr, INVS0, K1, KSPLIT0);
        reduce_h0_stats<<<NB, 256>>>(part, mb0, h0, pstat);
        stats_fin<<<HID, 128>>>(pstat, g0, be0, sc + 0 * HID, sh + 0 * HID);
    }

    // 3) layer 1
    conv_split<<<BATCH * K2P / 256, 256>>>(h0, sc + 0 * HID, sh + 0 * HID, a2);
    wsplit<<<HID * K2P / 256, 256>>>(mw1, w2h, w2l);
    {
        dim3 grid(HID / BN, BATCH / BM, 1);
        gemm_f16<<<grid, 256, SMEM_G>>>(a2, w2h, w2l, h1, mb1, INVS2, K2P, 1);
    }
    bn_pass1<<<NB, 256>>>(h1, pstat);
    stats_fin<<<HID, 128>>>(pstat, g1, be1, sc + 1 * HID, sh + 1 * HID);

    // 4) layer 2
    conv_split<<<BATCH * K2P / 256, 256>>>(h1, sc + 1 * HID, sh + 1 * HID, a2);
    wsplit<<<HID * K2P / 256, 256>>>(mw2, w2h, w2l);
    {
        dim3 grid(HID / BN, BATCH / BM, 1);
        gemm_f16<<<grid, 256, SMEM_G>>>(a2, w2h, w2l, h2, mb2, INVS2, K2P, 1);
    }
    bn_pass1<<<NB, 256>>>(h2, pstat);
    stats_fin<<<HID, 128>>>(pstat, g2, be2, sc + 2 * HID, sh + 2 * HID);

    // 5) final dot
    final_dot<<<(BATCH * 32 + 255) / 256, 256>>>(h2, sc + 2 * HID, sh + 2 * HID,
                                                 mw3, mb3, out);
}